// round 9
// baseline (speedup 1.0000x reference)
#include <cuda_runtime.h>
#include <cstdint>
#include <math.h>

// Problem constants
#define DIMC 1024
#define HC   16
#define DHC  64
#define BC   4
#define LC   4096
#define RC   512
#define SCALEF 0.125f   // 64^-0.5

// ---------------------------------------------------------------------------
// Device-global scratch
// ---------------------------------------------------------------------------
__device__ float g_Q [(size_t)BC * LC * DIMC];   // 64 MB (tf32-rounded, pre-scaled)
__device__ float g_K [(size_t)BC * RC * DIMC];   //  8 MB (tf32-rounded)
__device__ float g_V [(size_t)BC * RC * DIMC];   //  8 MB (tf32-rounded)
__device__ float g_O [(size_t)BC * LC * DIMC];   // 64 MB (attn out, tf32-rounded)
__device__ float g_Xr[(size_t)BC * LC * DIMC];   // 64 MB (x rounded to tf32)
__device__ float g_Cr[(size_t)BC * RC * DIMC];   //  8 MB (context rounded)
__device__ float g_WqT[(size_t)DIMC * DIMC];     //  4 MB each: W^T, tf32-rounded
__device__ float g_WkT[(size_t)DIMC * DIMC];
__device__ float g_WvT[(size_t)DIMC * DIMC];
__device__ float g_WoT[(size_t)DIMC * DIMC];

// ---------------------------------------------------------------------------
// Helpers
// ---------------------------------------------------------------------------
__device__ __forceinline__ uint32_t smem_u32(const void* p) {
    uint32_t a;
    asm("{ .reg .u64 t; cvta.to.shared.u64 t, %1; cvt.u32.u64 %0, t; }" : "=r"(a) : "l"(p));
    return a;
}
__device__ __forceinline__ float tf32_rn(float x) {
    float y;
    asm("cvt.rna.tf32.f32 %0, %1;" : "=f"(y) : "f"(x));
    return y;
}

#define CP_ASYNC16(dst, src) \
    asm volatile("cp.async.cg.shared.global [%0], [%1], 16;" :: "r"(dst), "l"(src) : "memory")
#define CP_COMMIT() asm volatile("cp.async.commit_group;" ::: "memory")
#define CP_WAIT(n)  asm volatile("cp.async.wait_group %0;" :: "n"(n) : "memory")

__device__ __forceinline__ void mma_tf32(float* c, const uint32_t* a, const uint32_t* b) {
    asm volatile(
        "mma.sync.aligned.m16n8k8.row.col.f32.tf32.tf32.f32 "
        "{%0,%1,%2,%3}, {%4,%5,%6,%7}, {%8,%9}, {%0,%1,%2,%3};"
        : "+f"(c[0]), "+f"(c[1]), "+f"(c[2]), "+f"(c[3])
        : "r"(a[0]), "r"(a[1]), "r"(a[2]), "r"(a[3]), "r"(b[0]), "r"(b[1]));
}

// ---------------------------------------------------------------------------
// Preprocessing kernels (round to tf32; transpose weights)
// ---------------------------------------------------------------------------
__global__ __launch_bounds__(256) void round_copy_kernel(const float* __restrict__ src,
                                                         float* __restrict__ dst, int n4) {
    int i = blockIdx.x * 256 + threadIdx.x;
    if (i < n4) {
        float4 v = ((const float4*)src)[i];
        v.x = tf32_rn(v.x); v.y = tf32_rn(v.y); v.z = tf32_rn(v.z); v.w = tf32_rn(v.w);
        ((float4*)dst)[i] = v;
    }
}

__global__ __launch_bounds__(256) void transpose_round_kernel(const float* __restrict__ W,
                                                              float* __restrict__ Wt,
                                                              float scale) {
    __shared__ float t[32][33];
    int x = blockIdx.x * 32 + threadIdx.x;
#pragma unroll
    for (int i = threadIdx.y; i < 32; i += 8) {
        int y = blockIdx.y * 32 + i;
        t[i][threadIdx.x] = tf32_rn(W[(size_t)y * DIMC + x] * scale);
    }
    __syncthreads();
    int xo = blockIdx.y * 32 + threadIdx.x;
#pragma unroll
    for (int i = threadIdx.y; i < 32; i += 8) {
        int yo = blockIdx.x * 32 + i;
        Wt[(size_t)yo * DIMC + xo] = t[threadIdx.x][i];
    }
}

// ---------------------------------------------------------------------------
// tf32 mma.sync GEMM v2: C[M,1024] = A[M,1024] @ Bt[N=1024,K=1024]^T
// CTA tile 256x128, BK=16, 3-stage cp.async, 256 threads,
// 8 warps (4 M x 2 N), warp tile 64x64 = 4x8 m16n8k8 tiles (mi=4, nj=8).
// round_out=1 -> write tf32-rounded C (for Q/K/V feeding attention mma).
// ---------------------------------------------------------------------------
#define BK 16
#define SK 20
#define BM 256
#define BN 128
#define A_FLOATS (BM * SK)              // 5120
#define B_FLOATS (BN * SK)              // 2560
#define STG_STRIDE (A_FLOATS + B_FLOATS)  // 7680 floats per stage
#define GSM_TOTAL (3 * STG_STRIDE * 4)    // 92160 B

__device__ __forceinline__ void load_stage(uint32_t sbase, const float* __restrict__ Ab,
                                           const float* __restrict__ Bb, int kt, int tid) {
    uint32_t sA = sbase;
    uint32_t sB = sbase + A_FLOATS * 4;
    const float* As_ = Ab + kt * BK;
    const float* Bs_ = Bb + kt * BK;
    // A: 256 rows x 4 granules = 1024; B: 128 rows x 4 granules = 512
#pragma unroll
    for (int i = 0; i < 4; i++) {
        int id = tid + i * 256;        // 0..1023
        int r = id >> 2;
        int c = id & 3;
        CP_ASYNC16(sA + (uint32_t)(r * SK * 4 + c * 16), As_ + (size_t)r * DIMC + c * 4);
    }
#pragma unroll
    for (int i = 0; i < 2; i++) {
        int id = tid + i * 256;        // 0..511
        int r = id >> 2;
        int c = id & 3;
        CP_ASYNC16(sB + (uint32_t)(r * SK * 4 + c * 16), Bs_ + (size_t)r * DIMC + c * 4);
    }
}

__global__ __launch_bounds__(256, 1) void mma_gemm_kernel(const float* __restrict__ A,
                                                          const float* __restrict__ Bt,
                                                          float* __restrict__ C,
                                                          int round_out) {
    extern __shared__ float sm[];
    const int tid = threadIdx.x;
    const int lane = tid & 31;
    const int g = lane >> 2;
    const int tg = lane & 3;
    const int wid = tid >> 5;
    const int wm = (wid & 3) * 64;     // warp M offset (4 warps along M)
    const int wn = (wid >> 2) * 64;    // warp N offset (2 warps along N)

    const float* Ab = A  + (size_t)blockIdx.y * BM * DIMC;
    const float* Bb = Bt + (size_t)blockIdx.x * BN * DIMC;
    uint32_t sb = smem_u32(sm);

    float acc[4][8][4];
#pragma unroll
    for (int mi = 0; mi < 4; mi++)
#pragma unroll
        for (int nj = 0; nj < 8; nj++)
#pragma unroll
            for (int q = 0; q < 4; q++) acc[mi][nj][q] = 0.f;

    load_stage(sb + 0 * STG_STRIDE * 4, Ab, Bb, 0, tid); CP_COMMIT();
    load_stage(sb + 1 * STG_STRIDE * 4, Ab, Bb, 1, tid); CP_COMMIT();

    const int NKT = DIMC / BK;   // 64
    for (int kt = 0; kt < NKT; kt++) {
        if (kt < NKT - 1) { CP_WAIT(1); } else { CP_WAIT(0); }
        __syncthreads();

        const float* St = sm + (kt % 3) * STG_STRIDE;
        const float* As_ = St + wm * SK;
        const float* Bs_ = St + A_FLOATS + wn * SK;

#pragma unroll
        for (int kk = 0; kk < BK; kk += 8) {
            uint32_t a[4][4], b[8][2];
#pragma unroll
            for (int mi = 0; mi < 4; mi++) {
                int r0 = mi * 16 + g;
                a[mi][0] = __float_as_uint(As_[r0 * SK + kk + tg]);
                a[mi][1] = __float_as_uint(As_[(r0 + 8) * SK + kk + tg]);
                a[mi][2] = __float_as_uint(As_[r0 * SK + kk + tg + 4]);
                a[mi][3] = __float_as_uint(As_[(r0 + 8) * SK + kk + tg + 4]);
            }
#pragma unroll
            for (int nj = 0; nj < 8; nj++) {
                int c0 = nj * 8 + g;
                b[nj][0] = __float_as_uint(Bs_[c0 * SK + kk + tg]);
                b[nj][1] = __float_as_uint(Bs_[c0 * SK + kk + tg + 4]);
            }
#pragma unroll
            for (int mi = 0; mi < 4; mi++)
#pragma unroll
                for (int nj = 0; nj < 8; nj++)
                    mma_tf32(acc[mi][nj], a[mi], b[nj]);
        }

        if (kt + 2 < NKT) {
            load_stage(sb + ((kt + 2) % 3) * STG_STRIDE * 4, Ab, Bb, kt + 2, tid);
            CP_COMMIT();
        }
    }

    if (round_out) {
#pragma unroll
        for (int mi = 0; mi < 4; mi++)
#pragma unroll
            for (int nj = 0; nj < 8; nj++)
#pragma unroll
                for (int q = 0; q < 4; q++) acc[mi][nj][q] = tf32_rn(acc[mi][nj][q]);
    }

    size_t rowb = (size_t)blockIdx.y * BM + wm + g;
    size_t colb = (size_t)blockIdx.x * BN + wn;
#pragma unroll
    for (int mi = 0; mi < 4; mi++) {
        float* C0 = C + (rowb + mi * 16) * DIMC + colb;
        float* C1 = C0 + 8 * DIMC;
#pragma unroll
        for (int nj = 0; nj < 8; nj++) {
            *(float2*)(C0 + nj * 8 + tg * 2) = make_float2(acc[mi][nj][0], acc[mi][nj][1]);
            *(float2*)(C1 + nj * 8 + tg * 2) = make_float2(acc[mi][nj][2], acc[mi][nj][3]);
        }
    }
}

// ---------------------------------------------------------------------------
// Tensor-core attention: one CTA = (b,h) x 64 q rows.
//   S(64x512) = Qs(64x64,pre-scaled) @ K^T   (tf32 mma, 4 chunks of 128, cp.async db)
//   softmax: 2 passes, unnormalized exp stored tf32, inv-sum deferred
//   O(64x64) = P(64x512) @ V                 (tf32 mma, V transposed in smem)
// ---------------------------------------------------------------------------
#define SSTR 516
#define QSTR 68
#define KSTR 68
#define VSTR 132
#define S_OFF   0
#define Q_OFF   33024
#define KB_OFF  37376
#define INV_OFF 54784
#define ATTN_SMEM ((INV_OFF + 64) * 4)   // 219,392 B

__global__ __launch_bounds__(256) void attn_mma_kernel() {
    extern __shared__ float sm[];
    float* Ss = sm + S_OFF;
    float* Qs = sm + Q_OFF;
    float* KB = sm + KB_OFF;
    float* sInv = sm + INV_OFF;
    uint32_t sb = smem_u32(sm);
    const uint32_t qb = sb + Q_OFF * 4;
    const uint32_t kb = sb + KB_OFF * 4;

    const int tid = threadIdx.x;
    const int lane = tid & 31;
    const int g = lane >> 2;
    const int tg = lane & 3;
    const int wid = tid >> 5;
    const int bh = blockIdx.y;
    const int b = bh >> 4;
    const int h = bh & 15;
    const int q0 = blockIdx.x * 64;

    const float* Qg = g_Q + ((size_t)(b * LC + q0)) * DIMC + h * DHC;
    const float* Kg = g_K + ((size_t)(b * RC)) * DIMC + h * DHC;
    const float* Vg = g_V + ((size_t)(b * RC)) * DIMC + h * DHC;

    // async prologue: Q tile (64x64) + K chunk 0 (128x64)
#pragma unroll
    for (int i = 0; i < 4; i++) {
        int id = tid + i * 256;
        int r = id >> 4, c = id & 15;
        CP_ASYNC16(qb + (uint32_t)((r * QSTR + c * 4) * 4), Qg + (size_t)r * DIMC + c * 4);
    }
#pragma unroll
    for (int i = 0; i < 8; i++) {
        int id = tid + i * 256;            // 0..2047
        int r = id >> 4, c = id & 15;      // 128 rows x 16 granules
        CP_ASYNC16(kb + (uint32_t)((r * KSTR + c * 4) * 4), Kg + (size_t)r * DIMC + c * 4);
    }
    CP_COMMIT();

    // ---- S phase: 8 warps as 2m x 4n (32x32 warp tiles) ----
    const int wmS = (wid & 1) * 32;
    const int wnS = (wid >> 1) * 32;
    for (int rc = 0; rc < 4; rc++) {
        CP_WAIT(0);
        __syncthreads();
        if (rc + 1 < 4) {
            uint32_t dstb = kb + (uint32_t)(((rc + 1) & 1) * 8704 * 4);
            const float* src = Kg + (size_t)(rc + 1) * 128 * DIMC;
#pragma unroll
            for (int i = 0; i < 8; i++) {
                int id = tid + i * 256;
                int r = id >> 4, c = id & 15;
                CP_ASYNC16(dstb + (uint32_t)((r * KSTR + c * 4) * 4), src + (size_t)r * DIMC + c * 4);
            }
            CP_COMMIT();
        }
        const float* Ksm = KB + (rc & 1) * 8704;
        float acc[2][4][4];
#pragma unroll
        for (int mi = 0; mi < 2; mi++)
#pragma unroll
            for (int nj = 0; nj < 4; nj++)
#pragma unroll
                for (int q = 0; q < 4; q++) acc[mi][nj][q] = 0.f;

#pragma unroll
        for (int kk = 0; kk < 64; kk += 8) {
            uint32_t a[2][4], bb[4][2];
#pragma unroll
            for (int mi = 0; mi < 2; mi++) {
                int r0 = wmS + mi * 16 + g;
                a[mi][0] = __float_as_uint(Qs[r0 * QSTR + kk + tg]);
                a[mi][1] = __float_as_uint(Qs[(r0 + 8) * QSTR + kk + tg]);
                a[mi][2] = __float_as_uint(Qs[r0 * QSTR + kk + tg + 4]);
                a[mi][3] = __float_as_uint(Qs[(r0 + 8) * QSTR + kk + tg + 4]);
            }
#pragma unroll
            for (int nj = 0; nj < 4; nj++) {
                int c0 = wnS + nj * 8 + g;
                bb[nj][0] = __float_as_uint(Ksm[c0 * KSTR + kk + tg]);
                bb[nj][1] = __float_as_uint(Ksm[c0 * KSTR + kk + tg + 4]);
            }
#pragma unroll
            for (int mi = 0; mi < 2; mi++)
#pragma unroll
                for (int nj = 0; nj < 4; nj++)
                    mma_tf32(acc[mi][nj], a[mi], bb[nj]);
        }
#pragma unroll
        for (int mi = 0; mi < 2; mi++) {
            int row = wmS + mi * 16 + g;
#pragma unroll
            for (int nj = 0; nj < 4; nj++) {
                int col = rc * 128 + wnS + nj * 8 + tg * 2;
                *(float2*)&Ss[row * SSTR + col]       = make_float2(acc[mi][nj][0], acc[mi][nj][1]);
                *(float2*)&Ss[(row + 8) * SSTR + col] = make_float2(acc[mi][nj][2], acc[mi][nj][3]);
            }
        }
    }
    __syncthreads();

    // ---- softmax: 2 passes; store unnormalized tf32 exp; keep 1/sum ----
    for (int r = wid; r < 64; r += 8) {
        float* row = Ss + r * SSTR;
        float m = -1e30f;
        for (int c = lane; c < 512; c += 32) m = fmaxf(m, row[c]);
#pragma unroll
        for (int o = 16; o > 0; o >>= 1) m = fmaxf(m, __shfl_xor_sync(0xffffffffu, m, o));
        float s = 0.f;
        for (int c = lane; c < 512; c += 32) {
            float e = tf32_rn(__expf(row[c] - m));
            row[c] = e;
            s += e;
        }
#pragma unroll
        for (int o = 16; o > 0; o >>= 1) s += __shfl_xor_sync(0xffffffffu, s, o);
        if (lane == 0) sInv[r] = 1.f / s;
    }

    // ---- PV phase: 8 warps as 4m x 2n (16x32 warp tiles) ----
    const int wmP = (wid & 3) * 16;
    const int wnP = (wid >> 2) * 32;
    float po[4][4];
#pragma unroll
    for (int nj = 0; nj < 4; nj++)
#pragma unroll
        for (int q = 0; q < 4; q++) po[nj][q] = 0.f;

    for (int rc = 0; rc < 4; rc++) {
        __syncthreads();
        // load V chunk transposed: Vt[d][r]
#pragma unroll
        for (int i = 0; i < 8; i++) {
            int id = tid + i * 256;
            int r = id & 127;
            int c = (id >> 7) * 4;
            float4 v = *(const float4*)(Vg + (size_t)(rc * 128 + r) * DIMC + c);
            KB[(c + 0) * VSTR + r] = v.x;
            KB[(c + 1) * VSTR + r] = v.y;
            KB[(c + 2) * VSTR + r] = v.z;
            KB[(c + 3) * VSTR + r] = v.w;
        }
        __syncthreads();
#pragma unroll
        for (int kk = 0; kk < 128; kk += 8) {
            uint32_t a[4], bb[4][2];
            int r0 = wmP + g;
            int colk = rc * 128 + kk + tg;
            a[0] = __float_as_uint(Ss[r0 * SSTR + colk]);
            a[1] = __float_as_uint(Ss[(r0 + 8) * SSTR + colk]);
            a[2] = __float_as_uint(Ss[r0 * SSTR + colk + 4]);
            a[3] = __float_as_uint(Ss[(r0 + 8) * SSTR + colk + 4]);
#pragma unroll
            for (int nj = 0; nj < 4; nj++) {
                int c0 = wnP + nj * 8 + g;
                bb[nj][0] = __float_as_uint(KB[c0 * VSTR + kk + tg]);
                bb[nj][1] = __float_as_uint(KB[c0 * VSTR + kk + tg + 4]);
            }
#pragma unroll
            for (int nj = 0; nj < 4; nj++)
                mma_tf32(po[nj], a, bb[nj]);
        }
    }

    // ---- epilogue: normalize (fp32), round to tf32, store to g_O ----
    float inv0 = sInv[wmP + g];
    float inv1 = sInv[wmP + g + 8];
    float* Og = g_O + ((size_t)(b * LC + q0 + wmP + g)) * DIMC + h * DHC + wnP;
#pragma unroll
    for (int nj = 0; nj < 4; nj++) {
        int col = nj * 8 + tg * 2;
        *(float2*)(Og + col) =
            make_float2(tf32_rn(po[nj][0] * inv0), tf32_rn(po[nj][1] * inv0));
        *(float2*)(Og + 8 * DIMC + col) =
            make_float2(tf32_rn(po[nj][2] * inv1), tf32_rn(po[nj][3] * inv1));
    }
}

// ---------------------------------------------------------------------------
// Launch
// ---------------------------------------------------------------------------
extern "C" void kernel_launch(void* const* d_in, const int* in_sizes, int n_in,
                              void* d_out, int out_size) {
    const float* x   = (const float*)d_in[0];
    const float* ctx = (const float*)d_in[1];
    const float* Wq  = (const float*)d_in[2];
    const float* Wk  = (const float*)d_in[3];
    const float* Wv  = (const float*)d_in[4];
    const float* Wo  = (const float*)d_in[5];
    float* out = (float*)d_out;

    void *pXr, *pCr, *pWqT, *pWkT, *pWvT, *pWoT, *pQ, *pK, *pV, *pO;
    cudaGetSymbolAddress(&pXr, g_Xr);
    cudaGetSymbolAddress(&pCr, g_Cr);
    cudaGetSymbolAddress(&pWqT, g_WqT);
    cudaGetSymbolAddress(&pWkT, g_WkT);
    cudaGetSymbolAddress(&pWvT, g_WvT);
    cudaGetSymbolAddress(&pWoT, g_WoT);
    cudaGetSymbolAddress(&pQ, g_Q);
    cudaGetSymbolAddress(&pK, g_K);
    cudaGetSymbolAddress(&pV, g_V);
    cudaGetSymbolAddress(&pO, g_O);

    cudaFuncSetAttribute(mma_gemm_kernel, cudaFuncAttributeMaxDynamicSharedMemorySize, GSM_TOTAL);
    cudaFuncSetAttribute(attn_mma_kernel, cudaFuncAttributeMaxDynamicSharedMemorySize, ATTN_SMEM);

    // Preprocess: round activations, transpose+round weights (Wq pre-scaled)
    round_copy_kernel<<<(BC * LC * DIMC / 4 + 255) / 256, 256>>>(x,   (float*)pXr, BC * LC * DIMC / 4);
    round_copy_kernel<<<(BC * RC * DIMC / 4 + 255) / 256, 256>>>(ctx, (float*)pCr, BC * RC * DIMC / 4);
    dim3 tb(32, 8), tg(DIMC / 32, DIMC / 32);
    transpose_round_kernel<<<tg, tb>>>(Wq, (float*)pWqT, SCALEF);
    transpose_round_kernel<<<tg, tb>>>(Wk, (float*)pWkT, 1.0f);
    transpose_round_kernel<<<tg, tb>>>(Wv, (float*)pWvT, 1.0f);
    transpose_round_kernel<<<tg, tb>>>(Wo, (float*)pWoT, 1.0f);

    // Projections (tf32 mma.sync), outputs rounded to tf32 for attention
    mma_gemm_kernel<<<dim3(DIMC / BN, (BC * LC) / BM), 256, GSM_TOTAL>>>((const float*)pXr, (const float*)pWqT, (float*)pQ, 1);
    mma_gemm_kernel<<<dim3(DIMC / BN, (BC * RC) / BM), 256, GSM_TOTAL>>>((const float*)pCr, (const float*)pWkT, (float*)pK, 1);
    mma_gemm_kernel<<<dim3(DIMC / BN, (BC * RC) / BM), 256, GSM_TOTAL>>>((const float*)pCr, (const float*)pWvT, (float*)pV, 1);

    // Attention (tf32 mma.sync)
    attn_mma_kernel<<<dim3(LC / 64, BC * HC), 256, ATTN_SMEM>>>();

    // Output projection (full-precision fp32 store)
    mma_gemm_kernel<<<dim3(DIMC / BN, (BC * LC) / BM), 256, GSM_TOTAL>>>((const float*)pO, (const float*)pWoT, out, 0);
}

// round 10
// speedup vs baseline: 1.1323x; 1.1323x over previous
#include <cuda_runtime.h>
#include <cstdint>
#include <math.h>

// Problem constants
#define DIMC 1024
#define HC   16
#define DHC  64
#define BC   4
#define LC   4096
#define RC   512
#define SCALEF 0.125f   // 64^-0.5

// ---------------------------------------------------------------------------
// Device-global scratch
// ---------------------------------------------------------------------------
__device__ float g_Q [(size_t)BC * LC * DIMC];   // 64 MB (tf32-rounded, pre-scaled)
__device__ float g_K [(size_t)BC * RC * DIMC];   //  8 MB (tf32-rounded)
__device__ float g_V [(size_t)BC * RC * DIMC];   //  8 MB (tf32-rounded)
__device__ float g_O [(size_t)BC * LC * DIMC];   // 64 MB (attn out, tf32-rounded)
__device__ float g_Xr[(size_t)BC * LC * DIMC];   // 64 MB (x rounded to tf32)
__device__ float g_Cr[(size_t)BC * RC * DIMC];   //  8 MB (context rounded)
__device__ float g_WqT[(size_t)DIMC * DIMC];     //  4 MB each: W^T, tf32-rounded
__device__ float g_WkT[(size_t)DIMC * DIMC];
__device__ float g_WvT[(size_t)DIMC * DIMC];
__device__ float g_WoT[(size_t)DIMC * DIMC];

// ---------------------------------------------------------------------------
// Helpers
// ---------------------------------------------------------------------------
__device__ __forceinline__ uint32_t smem_u32(const void* p) {
    uint32_t a;
    asm("{ .reg .u64 t; cvta.to.shared.u64 t, %1; cvt.u32.u64 %0, t; }" : "=r"(a) : "l"(p));
    return a;
}
__device__ __forceinline__ float tf32_rn(float x) {
    float y;
    asm("cvt.rna.tf32.f32 %0, %1;" : "=f"(y) : "f"(x));
    return y;
}

#define CP_ASYNC16(dst, src) \
    asm volatile("cp.async.cg.shared.global [%0], [%1], 16;" :: "r"(dst), "l"(src) : "memory")
#define CP_COMMIT() asm volatile("cp.async.commit_group;" ::: "memory")
#define CP_WAIT(n)  asm volatile("cp.async.wait_group %0;" :: "n"(n) : "memory")

__device__ __forceinline__ void mma_tf32(float* c, const uint32_t* a, const uint32_t* b) {
    asm volatile(
        "mma.sync.aligned.m16n8k8.row.col.f32.tf32.tf32.f32 "
        "{%0,%1,%2,%3}, {%4,%5,%6,%7}, {%8,%9}, {%0,%1,%2,%3};"
        : "+f"(c[0]), "+f"(c[1]), "+f"(c[2]), "+f"(c[3])
        : "r"(a[0]), "r"(a[1]), "r"(a[2]), "r"(a[3]), "r"(b[0]), "r"(b[1]));
}

// ---------------------------------------------------------------------------
// Preprocessing kernels (round to tf32; transpose weights)
// ---------------------------------------------------------------------------
__global__ __launch_bounds__(256) void round_copy_kernel(const float* __restrict__ src,
                                                         float* __restrict__ dst, int n4) {
    int i = blockIdx.x * 256 + threadIdx.x;
    if (i < n4) {
        float4 v = ((const float4*)src)[i];
        v.x = tf32_rn(v.x); v.y = tf32_rn(v.y); v.z = tf32_rn(v.z); v.w = tf32_rn(v.w);
        ((float4*)dst)[i] = v;
    }
}

// One launch transposes all 4 weights; blockIdx.z selects which.
__global__ __launch_bounds__(256) void transpose_all_kernel(const float* __restrict__ W0,
                                                            const float* __restrict__ W1,
                                                            const float* __restrict__ W2,
                                                            const float* __restrict__ W3,
                                                            float* __restrict__ T0,
                                                            float* __restrict__ T1,
                                                            float* __restrict__ T2,
                                                            float* __restrict__ T3) {
    __shared__ float t[32][33];
    const float* W;
    float* Wt;
    float scale = 1.0f;
    switch (blockIdx.z) {
        case 0: W = W0; Wt = T0; scale = SCALEF; break;
        case 1: W = W1; Wt = T1; break;
        case 2: W = W2; Wt = T2; break;
        default: W = W3; Wt = T3; break;
    }
    int tx = threadIdx.x & 31;
    int ty = threadIdx.x >> 5;
    int x = blockIdx.x * 32 + tx;
#pragma unroll
    for (int i = ty; i < 32; i += 8) {
        int y = blockIdx.y * 32 + i;
        t[i][tx] = tf32_rn(W[(size_t)y * DIMC + x] * scale);
    }
    __syncthreads();
    int xo = blockIdx.y * 32 + tx;
#pragma unroll
    for (int i = ty; i < 32; i += 8) {
        int yo = blockIdx.x * 32 + i;
        Wt[(size_t)yo * DIMC + xo] = t[tx][i];
    }
}

// ---------------------------------------------------------------------------
// tf32 mma.sync GEMM: C[M,1024] = A[M,1024] @ Bt[N=1024,K=1024]^T
// CTA tile 128x128, BK=16, 3-stage cp.async, 256 threads,
// 8 warps (4 M x 2 N), warp tile 32x64. 2 CTAs/SM via launch_bounds.
// round_out=1 -> write tf32-rounded C (for Q/K/V feeding attention mma).
// ---------------------------------------------------------------------------
#define BK 16
#define SK 20
#define STG_FLOATS (128 * SK)
#define STG_STRIDE (2 * STG_FLOATS)
#define GSM_TOTAL (3 * STG_STRIDE * 4)  // 61440 B

__device__ __forceinline__ void load_stage(uint32_t sbase, const float* __restrict__ Ab,
                                           const float* __restrict__ Bb, int kt, int tid) {
    uint32_t sA = sbase;
    uint32_t sB = sbase + STG_FLOATS * 4;
    const float* As_ = Ab + kt * BK;
    const float* Bs_ = Bb + kt * BK;
#pragma unroll
    for (int i = 0; i < 2; i++) {
        int id = tid + i * 256;
        int r = id >> 2;
        int c = id & 3;
        CP_ASYNC16(sA + (uint32_t)(r * SK * 4 + c * 16), As_ + (size_t)r * DIMC + c * 4);
        CP_ASYNC16(sB + (uint32_t)(r * SK * 4 + c * 16), Bs_ + (size_t)r * DIMC + c * 4);
    }
}

__global__ __launch_bounds__(256, 2) void mma_gemm_kernel(const float* __restrict__ A,
                                                          const float* __restrict__ Bt,
                                                          float* __restrict__ C,
                                                          int round_out) {
    extern __shared__ float sm[];
    const int tid = threadIdx.x;
    const int lane = tid & 31;
    const int g = lane >> 2;
    const int tg = lane & 3;
    const int wid = tid >> 5;
    const int wm = (wid & 3) * 32;
    const int wn = (wid >> 2) * 64;

    const float* Ab = A  + (size_t)blockIdx.y * 128 * DIMC;
    const float* Bb = Bt + (size_t)blockIdx.x * 128 * DIMC;
    uint32_t sb = smem_u32(sm);

    float acc[2][8][4];
#pragma unroll
    for (int mi = 0; mi < 2; mi++)
#pragma unroll
        for (int nj = 0; nj < 8; nj++)
#pragma unroll
            for (int q = 0; q < 4; q++) acc[mi][nj][q] = 0.f;

    load_stage(sb + 0 * STG_STRIDE * 4, Ab, Bb, 0, tid); CP_COMMIT();
    load_stage(sb + 1 * STG_STRIDE * 4, Ab, Bb, 1, tid); CP_COMMIT();

    const int NKT = DIMC / BK;
    for (int kt = 0; kt < NKT; kt++) {
        if (kt < NKT - 1) { CP_WAIT(1); } else { CP_WAIT(0); }
        __syncthreads();

        const float* St = sm + (kt % 3) * STG_STRIDE;
        const float* As_ = St + wm * SK;
        const float* Bs_ = St + STG_FLOATS + wn * SK;

#pragma unroll
        for (int kk = 0; kk < BK; kk += 8) {
            uint32_t a[2][4], b[8][2];
#pragma unroll
            for (int mi = 0; mi < 2; mi++) {
                int r0 = mi * 16 + g;
                a[mi][0] = __float_as_uint(As_[r0 * SK + kk + tg]);
                a[mi][1] = __float_as_uint(As_[(r0 + 8) * SK + kk + tg]);
                a[mi][2] = __float_as_uint(As_[r0 * SK + kk + tg + 4]);
                a[mi][3] = __float_as_uint(As_[(r0 + 8) * SK + kk + tg + 4]);
            }
#pragma unroll
            for (int nj = 0; nj < 8; nj++) {
                int c0 = nj * 8 + g;
                b[nj][0] = __float_as_uint(Bs_[c0 * SK + kk + tg]);
                b[nj][1] = __float_as_uint(Bs_[c0 * SK + kk + tg + 4]);
            }
#pragma unroll
            for (int mi = 0; mi < 2; mi++)
#pragma unroll
                for (int nj = 0; nj < 8; nj++)
                    mma_tf32(acc[mi][nj], a[mi], b[nj]);
        }

        if (kt + 2 < NKT) {
            load_stage(sb + ((kt + 2) % 3) * STG_STRIDE * 4, Ab, Bb, kt + 2, tid);
            CP_COMMIT();
        }
    }

    if (round_out) {
#pragma unroll
        for (int mi = 0; mi < 2; mi++)
#pragma unroll
            for (int nj = 0; nj < 8; nj++)
#pragma unroll
                for (int q = 0; q < 4; q++) acc[mi][nj][q] = tf32_rn(acc[mi][nj][q]);
    }

    size_t rowb = (size_t)blockIdx.y * 128 + wm + g;
    size_t colb = (size_t)blockIdx.x * 128 + wn;
#pragma unroll
    for (int mi = 0; mi < 2; mi++) {
        float* C0 = C + (rowb + mi * 16) * DIMC + colb;
        float* C1 = C0 + 8 * DIMC;
#pragma unroll
        for (int nj = 0; nj < 8; nj++) {
            *(float2*)(C0 + nj * 8 + tg * 2) = make_float2(acc[mi][nj][0], acc[mi][nj][1]);
            *(float2*)(C1 + nj * 8 + tg * 2) = make_float2(acc[mi][nj][2], acc[mi][nj][3]);
        }
    }
}

// ---------------------------------------------------------------------------
// Tensor-core attention: one CTA = (b,h) x 64 q rows.
//   S(64x512) = Qs(64x64,pre-scaled) @ K^T   (tf32 mma, 4 chunks of 128, cp.async db)
//   softmax: 2 passes, unnormalized exp stored tf32, inv-sum deferred
//   O(64x64) = P(64x512) @ V                 (tf32 mma, V transposed in smem)
// ---------------------------------------------------------------------------
#define SSTR 516
#define QSTR 68
#define KSTR 68
#define VSTR 132
#define S_OFF   0
#define Q_OFF   33024
#define KB_OFF  37376
#define INV_OFF 54784
#define ATTN_SMEM ((INV_OFF + 64) * 4)   // 219,392 B

__global__ __launch_bounds__(256) void attn_mma_kernel() {
    extern __shared__ float sm[];
    float* Ss = sm + S_OFF;
    float* Qs = sm + Q_OFF;
    float* KB = sm + KB_OFF;
    float* sInv = sm + INV_OFF;
    uint32_t sb = smem_u32(sm);
    const uint32_t qb = sb + Q_OFF * 4;
    const uint32_t kb = sb + KB_OFF * 4;

    const int tid = threadIdx.x;
    const int lane = tid & 31;
    const int g = lane >> 2;
    const int tg = lane & 3;
    const int wid = tid >> 5;
    const int bh = blockIdx.y;
    const int b = bh >> 4;
    const int h = bh & 15;
    const int q0 = blockIdx.x * 64;

    const float* Qg = g_Q + ((size_t)(b * LC + q0)) * DIMC + h * DHC;
    const float* Kg = g_K + ((size_t)(b * RC)) * DIMC + h * DHC;
    const float* Vg = g_V + ((size_t)(b * RC)) * DIMC + h * DHC;

    // async prologue: Q tile (64x64) + K chunk 0 (128x64)
#pragma unroll
    for (int i = 0; i < 4; i++) {
        int id = tid + i * 256;
        int r = id >> 4, c = id & 15;
        CP_ASYNC16(qb + (uint32_t)((r * QSTR + c * 4) * 4), Qg + (size_t)r * DIMC + c * 4);
    }
#pragma unroll
    for (int i = 0; i < 8; i++) {
        int id = tid + i * 256;            // 0..2047
        int r = id >> 4, c = id & 15;      // 128 rows x 16 granules
        CP_ASYNC16(kb + (uint32_t)((r * KSTR + c * 4) * 4), Kg + (size_t)r * DIMC + c * 4);
    }
    CP_COMMIT();

    // ---- S phase: 8 warps as 2m x 4n (32x32 warp tiles) ----
    const int wmS = (wid & 1) * 32;
    const int wnS = (wid >> 1) * 32;
    for (int rc = 0; rc < 4; rc++) {
        CP_WAIT(0);
        __syncthreads();
        if (rc + 1 < 4) {
            uint32_t dstb = kb + (uint32_t)(((rc + 1) & 1) * 8704 * 4);
            const float* src = Kg + (size_t)(rc + 1) * 128 * DIMC;
#pragma unroll
            for (int i = 0; i < 8; i++) {
                int id = tid + i * 256;
                int r = id >> 4, c = id & 15;
                CP_ASYNC16(dstb + (uint32_t)((r * KSTR + c * 4) * 4), src + (size_t)r * DIMC + c * 4);
            }
            CP_COMMIT();
        }
        const float* Ksm = KB + (rc & 1) * 8704;
        float acc[2][4][4];
#pragma unroll
        for (int mi = 0; mi < 2; mi++)
#pragma unroll
            for (int nj = 0; nj < 4; nj++)
#pragma unroll
                for (int q = 0; q < 4; q++) acc[mi][nj][q] = 0.f;

#pragma unroll
        for (int kk = 0; kk < 64; kk += 8) {
            uint32_t a[2][4], bb[4][2];
#pragma unroll
            for (int mi = 0; mi < 2; mi++) {
                int r0 = wmS + mi * 16 + g;
                a[mi][0] = __float_as_uint(Qs[r0 * QSTR + kk + tg]);
                a[mi][1] = __float_as_uint(Qs[(r0 + 8) * QSTR + kk + tg]);
                a[mi][2] = __float_as_uint(Qs[r0 * QSTR + kk + tg + 4]);
                a[mi][3] = __float_as_uint(Qs[(r0 + 8) * QSTR + kk + tg + 4]);
            }
#pragma unroll
            for (int nj = 0; nj < 4; nj++) {
                int c0 = wnS + nj * 8 + g;
                bb[nj][0] = __float_as_uint(Ksm[c0 * KSTR + kk + tg]);
                bb[nj][1] = __float_as_uint(Ksm[c0 * KSTR + kk + tg + 4]);
            }
#pragma unroll
            for (int mi = 0; mi < 2; mi++)
#pragma unroll
                for (int nj = 0; nj < 4; nj++)
                    mma_tf32(acc[mi][nj], a[mi], bb[nj]);
        }
#pragma unroll
        for (int mi = 0; mi < 2; mi++) {
            int row = wmS + mi * 16 + g;
#pragma unroll
            for (int nj = 0; nj < 4; nj++) {
                int col = rc * 128 + wnS + nj * 8 + tg * 2;
                *(float2*)&Ss[row * SSTR + col]       = make_float2(acc[mi][nj][0], acc[mi][nj][1]);
                *(float2*)&Ss[(row + 8) * SSTR + col] = make_float2(acc[mi][nj][2], acc[mi][nj][3]);
            }
        }
    }
    __syncthreads();

    // ---- softmax: 2 passes; store unnormalized tf32 exp; keep 1/sum ----
    for (int r = wid; r < 64; r += 8) {
        float* row = Ss + r * SSTR;
        float m = -1e30f;
        for (int c = lane; c < 512; c += 32) m = fmaxf(m, row[c]);
#pragma unroll
        for (int o = 16; o > 0; o >>= 1) m = fmaxf(m, __shfl_xor_sync(0xffffffffu, m, o));
        float s = 0.f;
        for (int c = lane; c < 512; c += 32) {
            float e = tf32_rn(__expf(row[c] - m));
            row[c] = e;
            s += e;
        }
#pragma unroll
        for (int o = 16; o > 0; o >>= 1) s += __shfl_xor_sync(0xffffffffu, s, o);
        if (lane == 0) sInv[r] = 1.f / s;
    }

    // ---- PV phase: 8 warps as 4m x 2n (16x32 warp tiles) ----
    const int wmP = (wid & 3) * 16;
    const int wnP = (wid >> 2) * 32;
    float po[4][4];
#pragma unroll
    for (int nj = 0; nj < 4; nj++)
#pragma unroll
        for (int q = 0; q < 4; q++) po[nj][q] = 0.f;

    for (int rc = 0; rc < 4; rc++) {
        __syncthreads();
        // load V chunk transposed: Vt[d][r]
#pragma unroll
        for (int i = 0; i < 8; i++) {
            int id = tid + i * 256;
            int r = id & 127;
            int c = (id >> 7) * 4;
            float4 v = *(const float4*)(Vg + (size_t)(rc * 128 + r) * DIMC + c);
            KB[(c + 0) * VSTR + r] = v.x;
            KB[(c + 1) * VSTR + r] = v.y;
            KB[(c + 2) * VSTR + r] = v.z;
            KB[(c + 3) * VSTR + r] = v.w;
        }
        __syncthreads();
#pragma unroll
        for (int kk = 0; kk < 128; kk += 8) {
            uint32_t a[4], bb[4][2];
            int r0 = wmP + g;
            int colk = rc * 128 + kk + tg;
            a[0] = __float_as_uint(Ss[r0 * SSTR + colk]);
            a[1] = __float_as_uint(Ss[(r0 + 8) * SSTR + colk]);
            a[2] = __float_as_uint(Ss[r0 * SSTR + colk + 4]);
            a[3] = __float_as_uint(Ss[(r0 + 8) * SSTR + colk + 4]);
#pragma unroll
            for (int nj = 0; nj < 4; nj++) {
                int c0 = wnP + nj * 8 + g;
                bb[nj][0] = __float_as_uint(KB[c0 * VSTR + kk + tg]);
                bb[nj][1] = __float_as_uint(KB[c0 * VSTR + kk + tg + 4]);
            }
#pragma unroll
            for (int nj = 0; nj < 4; nj++)
                mma_tf32(po[nj], a, bb[nj]);
        }
    }

    // ---- epilogue: normalize (fp32), round to tf32, store to g_O ----
    float inv0 = sInv[wmP + g];
    float inv1 = sInv[wmP + g + 8];
    float* Og = g_O + ((size_t)(b * LC + q0 + wmP + g)) * DIMC + h * DHC + wnP;
#pragma unroll
    for (int nj = 0; nj < 4; nj++) {
        int col = nj * 8 + tg * 2;
        *(float2*)(Og + col) =
            make_float2(tf32_rn(po[nj][0] * inv0), tf32_rn(po[nj][1] * inv0));
        *(float2*)(Og + 8 * DIMC + col) =
            make_float2(tf32_rn(po[nj][2] * inv1), tf32_rn(po[nj][3] * inv1));
    }
}

// ---------------------------------------------------------------------------
// Launch
// ---------------------------------------------------------------------------
extern "C" void kernel_launch(void* const* d_in, const int* in_sizes, int n_in,
                              void* d_out, int out_size) {
    const float* x   = (const float*)d_in[0];
    const float* ctx = (const float*)d_in[1];
    const float* Wq  = (const float*)d_in[2];
    const float* Wk  = (const float*)d_in[3];
    const float* Wv  = (const float*)d_in[4];
    const float* Wo  = (const float*)d_in[5];
    float* out = (float*)d_out;

    void *pXr, *pCr, *pWqT, *pWkT, *pWvT, *pWoT, *pQ, *pK, *pV, *pO;
    cudaGetSymbolAddress(&pXr, g_Xr);
    cudaGetSymbolAddress(&pCr, g_Cr);
    cudaGetSymbolAddress(&pWqT, g_WqT);
    cudaGetSymbolAddress(&pWkT, g_WkT);
    cudaGetSymbolAddress(&pWvT, g_WvT);
    cudaGetSymbolAddress(&pWoT, g_WoT);
    cudaGetSymbolAddress(&pQ, g_Q);
    cudaGetSymbolAddress(&pK, g_K);
    cudaGetSymbolAddress(&pV, g_V);
    cudaGetSymbolAddress(&pO, g_O);

    cudaFuncSetAttribute(mma_gemm_kernel, cudaFuncAttributeMaxDynamicSharedMemorySize, GSM_TOTAL);
    cudaFuncSetAttribute(attn_mma_kernel, cudaFuncAttributeMaxDynamicSharedMemorySize, ATTN_SMEM);

    // Preprocess (launch order arranged so ncu -s 5 profiles the big Q-GEMM)
    round_copy_kernel<<<(BC * LC * DIMC / 4 + 255) / 256, 256>>>(x,   (float*)pXr, BC * LC * DIMC / 4);   // 0
    round_copy_kernel<<<(BC * RC * DIMC / 4 + 255) / 256, 256>>>(ctx, (float*)pCr, BC * RC * DIMC / 4);   // 1
    dim3 tg3(DIMC / 32, DIMC / 32, 4);
    transpose_all_kernel<<<tg3, 256>>>(Wq, Wk, Wv, Wo,                                                     // 2
                                       (float*)pWqT, (float*)pWkT, (float*)pWvT, (float*)pWoT);

    // Small projections first (K, V), then Q (profiled), then attention, then O
    mma_gemm_kernel<<<dim3(DIMC / 128, (BC * RC) / 128), 256, GSM_TOTAL>>>((const float*)pCr, (const float*)pWkT, (float*)pK, 1);  // 3
    mma_gemm_kernel<<<dim3(DIMC / 128, (BC * RC) / 128), 256, GSM_TOTAL>>>((const float*)pCr, (const float*)pWvT, (float*)pV, 1);  // 4
    mma_gemm_kernel<<<dim3(DIMC / 128, (BC * LC) / 128), 256, GSM_TOTAL>>>((const float*)pXr, (const float*)pWqT, (float*)pQ, 1);  // 5 <- ncu
    attn_mma_kernel<<<dim3(LC / 64, BC * HC), 256, ATTN_SMEM>>>();                                                                  // 6
    mma_gemm_kernel<<<dim3(DIMC / 128, (BC * LC) / 128), 256, GSM_TOTAL>>>((const float*)pO, (const float*)pWoT, out, 0);           // 7
}

// round 11
// speedup vs baseline: 1.1924x; 1.0531x over previous
#include <cuda_runtime.h>
#include <cstdint>
#include <math.h>

// Problem constants
#define DIMC 1024
#define HC   16
#define DHC  64
#define BC   4
#define LC   4096
#define RC   512
#define SCALEF 0.125f   // 64^-0.5

// ---------------------------------------------------------------------------
// Device-global scratch
// ---------------------------------------------------------------------------
__device__ float g_Q [(size_t)BC * LC * DIMC];
__device__ float g_K [(size_t)BC * RC * DIMC];
__device__ float g_V [(size_t)BC * RC * DIMC];
__device__ float g_O [(size_t)BC * LC * DIMC];
__device__ float g_Xr[(size_t)BC * LC * DIMC];
__device__ float g_Cr[(size_t)BC * RC * DIMC];
__device__ float g_WqT[(size_t)DIMC * DIMC];
__device__ float g_WkT[(size_t)DIMC * DIMC];
__device__ float g_WvT[(size_t)DIMC * DIMC];
__device__ float g_WoT[(size_t)DIMC * DIMC];

// ---------------------------------------------------------------------------
// Helpers
// ---------------------------------------------------------------------------
__device__ __forceinline__ uint32_t smem_u32(const void* p) {
    uint32_t a;
    asm("{ .reg .u64 t; cvta.to.shared.u64 t, %1; cvt.u32.u64 %0, t; }" : "=r"(a) : "l"(p));
    return a;
}
__device__ __forceinline__ float tf32_rn(float x) {
    float y;
    asm("cvt.rna.tf32.f32 %0, %1;" : "=f"(y) : "f"(x));
    return y;
}

#define CP_ASYNC16(dst, src) \
    asm volatile("cp.async.cg.shared.global [%0], [%1], 16;" :: "r"(dst), "l"(src) : "memory")
#define CP_COMMIT() asm volatile("cp.async.commit_group;" ::: "memory")
#define CP_WAIT(n)  asm volatile("cp.async.wait_group %0;" :: "n"(n) : "memory")

__device__ __forceinline__ void mma_tf32(float* c, const uint32_t* a, const uint32_t* b) {
    asm volatile(
        "mma.sync.aligned.m16n8k8.row.col.f32.tf32.tf32.f32 "
        "{%0,%1,%2,%3}, {%4,%5,%6,%7}, {%8,%9}, {%0,%1,%2,%3};"
        : "+f"(c[0]), "+f"(c[1]), "+f"(c[2]), "+f"(c[3])
        : "r"(a[0]), "r"(a[1]), "r"(a[2]), "r"(a[3]), "r"(b[0]), "r"(b[1]));
}

// ldmatrix x4: four 8x4-b32 tiles; lane l of tile -> (row l/4, col l%4)
__device__ __forceinline__ void ldmx4(uint32_t& r0, uint32_t& r1, uint32_t& r2, uint32_t& r3,
                                      uint32_t addr) {
    asm volatile("ldmatrix.sync.aligned.m8n8.x4.shared.b16 {%0,%1,%2,%3}, [%4];"
                 : "=r"(r0), "=r"(r1), "=r"(r2), "=r"(r3) : "r"(addr));
}

// ---------------------------------------------------------------------------
// Preprocessing kernels
// ---------------------------------------------------------------------------
__global__ __launch_bounds__(256) void round_copy_kernel(const float* __restrict__ src,
                                                         float* __restrict__ dst, int n4) {
    int i = blockIdx.x * 256 + threadIdx.x;
    if (i < n4) {
        float4 v = ((const float4*)src)[i];
        v.x = tf32_rn(v.x); v.y = tf32_rn(v.y); v.z = tf32_rn(v.z); v.w = tf32_rn(v.w);
        ((float4*)dst)[i] = v;
    }
}

__global__ __launch_bounds__(256) void transpose_all_kernel(const float* __restrict__ W0,
                                                            const float* __restrict__ W1,
                                                            const float* __restrict__ W2,
                                                            const float* __restrict__ W3,
                                                            float* __restrict__ T0,
                                                            float* __restrict__ T1,
                                                            float* __restrict__ T2,
                                                            float* __restrict__ T3) {
    __shared__ float t[32][33];
    const float* W;
    float* Wt;
    float scale = 1.0f;
    switch (blockIdx.z) {
        case 0: W = W0; Wt = T0; scale = SCALEF; break;
        case 1: W = W1; Wt = T1; break;
        case 2: W = W2; Wt = T2; break;
        default: W = W3; Wt = T3; break;
    }
    int tx = threadIdx.x & 31;
    int ty = threadIdx.x >> 5;
    int x = blockIdx.x * 32 + tx;
#pragma unroll
    for (int i = ty; i < 32; i += 8) {
        int y = blockIdx.y * 32 + i;
        t[i][tx] = tf32_rn(W[(size_t)y * DIMC + x] * scale);
    }
    __syncthreads();
    int xo = blockIdx.y * 32 + tx;
#pragma unroll
    for (int i = ty; i < 32; i += 8) {
        int yo = blockIdx.x * 32 + i;
        Wt[(size_t)yo * DIMC + xo] = t[tx][i];
    }
}

// ---------------------------------------------------------------------------
// tf32 mma.sync GEMM: 128x128 CTA tile, BK=16, 3-stage cp.async, ldmatrix frags
// ---------------------------------------------------------------------------
#define BK 16
#define SK 20
#define STG_FLOATS (128 * SK)
#define STG_STRIDE (2 * STG_FLOATS)
#define GSM_TOTAL (3 * STG_STRIDE * 4)  // 61440 B

__device__ __forceinline__ void load_stage(uint32_t sbase, const float* __restrict__ Ab,
                                           const float* __restrict__ Bb, int kt, int tid) {
    uint32_t sA = sbase;
    uint32_t sB = sbase + STG_FLOATS * 4;
    const float* As_ = Ab + kt * BK;
    const float* Bs_ = Bb + kt * BK;
#pragma unroll
    for (int i = 0; i < 2; i++) {
        int id = tid + i * 256;
        int r = id >> 2;
        int c = id & 3;
        CP_ASYNC16(sA + (uint32_t)(r * SK * 4 + c * 16), As_ + (size_t)r * DIMC + c * 4);
        CP_ASYNC16(sB + (uint32_t)(r * SK * 4 + c * 16), Bs_ + (size_t)r * DIMC + c * 4);
    }
}

__global__ __launch_bounds__(256, 2) void mma_gemm_kernel(const float* __restrict__ A,
                                                          const float* __restrict__ Bt,
                                                          float* __restrict__ C,
                                                          int round_out) {
    extern __shared__ float sm[];
    const int tid = threadIdx.x;
    const int lane = tid & 31;
    const int g = lane >> 2;
    const int tg = lane & 3;
    const int wid = tid >> 5;
    const int wm = (wid & 3) * 32;
    const int wn = (wid >> 2) * 64;

    // ldmatrix per-lane row/col selectors
    const int a_row = (lane & 7) + ((lane >> 3) & 1) * 8;   // +8 for mats 1,3
    const int a_kof = (lane >> 4) * 4;                      // +4k for mats 2,3
    const int b_row = (lane & 7) + (lane >> 4) * 8;         // +8n for mats 2,3
    const int b_kof = ((lane >> 3) & 1) * 4;                // +4k for mats 1,3

    const float* Ab = A  + (size_t)blockIdx.y * 128 * DIMC;
    const float* Bb = Bt + (size_t)blockIdx.x * 128 * DIMC;
    uint32_t sb = smem_u32(sm);

    float acc[2][8][4];
#pragma unroll
    for (int mi = 0; mi < 2; mi++)
#pragma unroll
        for (int nj = 0; nj < 8; nj++)
#pragma unroll
            for (int q = 0; q < 4; q++) acc[mi][nj][q] = 0.f;

    load_stage(sb + 0 * STG_STRIDE * 4, Ab, Bb, 0, tid); CP_COMMIT();
    load_stage(sb + 1 * STG_STRIDE * 4, Ab, Bb, 1, tid); CP_COMMIT();

    const uint32_t a_lm = (uint32_t)(((wm + a_row) * SK + a_kof) * 4);
    const uint32_t b_lm = (uint32_t)(STG_FLOATS * 4 + ((wn + b_row) * SK + b_kof) * 4);

    const int NKT = DIMC / BK;
    for (int kt = 0; kt < NKT; kt++) {
        if (kt < NKT - 1) { CP_WAIT(1); } else { CP_WAIT(0); }
        __syncthreads();

        uint32_t stg = sb + (uint32_t)((kt % 3) * STG_STRIDE * 4);
        uint32_t aab = stg + a_lm;
        uint32_t bbb = stg + b_lm;

#pragma unroll
        for (int kk = 0; kk < BK; kk += 8) {
            uint32_t a[2][4], b[8][2];
#pragma unroll
            for (int mi = 0; mi < 2; mi++)
                ldmx4(a[mi][0], a[mi][1], a[mi][2], a[mi][3],
                      aab + (uint32_t)((mi * 16 * SK + kk) * 4));
#pragma unroll
            for (int njg = 0; njg < 8; njg += 2)
                ldmx4(b[njg][0], b[njg][1], b[njg + 1][0], b[njg + 1][1],
                      bbb + (uint32_t)((njg * 8 * SK + kk) * 4));
#pragma unroll
            for (int mi = 0; mi < 2; mi++)
#pragma unroll
                for (int nj = 0; nj < 8; nj++)
                    mma_tf32(acc[mi][nj], a[mi], b[nj]);
        }

        if (kt + 2 < NKT) {
            load_stage(sb + ((kt + 2) % 3) * STG_STRIDE * 4, Ab, Bb, kt + 2, tid);
            CP_COMMIT();
        }
    }

    if (round_out) {
#pragma unroll
        for (int mi = 0; mi < 2; mi++)
#pragma unroll
            for (int nj = 0; nj < 8; nj++)
#pragma unroll
                for (int q = 0; q < 4; q++) acc[mi][nj][q] = tf32_rn(acc[mi][nj][q]);
    }

    size_t rowb = (size_t)blockIdx.y * 128 + wm + g;
    size_t colb = (size_t)blockIdx.x * 128 + wn;
#pragma unroll
    for (int mi = 0; mi < 2; mi++) {
        float* C0 = C + (rowb + mi * 16) * DIMC + colb;
        float* C1 = C0 + 8 * DIMC;
#pragma unroll
        for (int nj = 0; nj < 8; nj++) {
            *(float2*)(C0 + nj * 8 + tg * 2) = make_float2(acc[mi][nj][0], acc[mi][nj][1]);
            *(float2*)(C1 + nj * 8 + tg * 2) = make_float2(acc[mi][nj][2], acc[mi][nj][3]);
        }
    }
}

// ---------------------------------------------------------------------------
// Tensor-core attention (ldmatrix frags): one CTA = (b,h) x 64 q rows.
// ---------------------------------------------------------------------------
#define SSTR 516
#define QSTR 68
#define KSTR 68
#define VSTR 132
#define S_OFF   0
#define Q_OFF   33024
#define KB_OFF  37376
#define INV_OFF 54784
#define ATTN_SMEM ((INV_OFF + 64) * 4)   // 219,392 B

__global__ __launch_bounds__(256) void attn_mma_kernel() {
    extern __shared__ float sm[];
    float* Ss = sm + S_OFF;
    float* KB = sm + KB_OFF;
    float* sInv = sm + INV_OFF;
    uint32_t sb = smem_u32(sm);
    const uint32_t qb = sb + Q_OFF * 4;
    const uint32_t kb = sb + KB_OFF * 4;

    const int tid = threadIdx.x;
    const int lane = tid & 31;
    const int g = lane >> 2;
    const int tg = lane & 3;
    const int wid = tid >> 5;
    const int bh = blockIdx.y;
    const int b = bh >> 4;
    const int h = bh & 15;
    const int q0 = blockIdx.x * 64;

    const int a_row = (lane & 7) + ((lane >> 3) & 1) * 8;
    const int a_kof = (lane >> 4) * 4;
    const int b_row = (lane & 7) + (lane >> 4) * 8;
    const int b_kof = ((lane >> 3) & 1) * 4;

    const float* Qg = g_Q + ((size_t)(b * LC + q0)) * DIMC + h * DHC;
    const float* Kg = g_K + ((size_t)(b * RC)) * DIMC + h * DHC;
    const float* Vg = g_V + ((size_t)(b * RC)) * DIMC + h * DHC;

    // async prologue: Q tile (64x64) + K chunk 0 (128x64)
#pragma unroll
    for (int i = 0; i < 4; i++) {
        int id = tid + i * 256;
        int r = id >> 4, c = id & 15;
        CP_ASYNC16(qb + (uint32_t)((r * QSTR + c * 4) * 4), Qg + (size_t)r * DIMC + c * 4);
    }
#pragma unroll
    for (int i = 0; i < 8; i++) {
        int id = tid + i * 256;
        int r = id >> 4, c = id & 15;
        CP_ASYNC16(kb + (uint32_t)((r * KSTR + c * 4) * 4), Kg + (size_t)r * DIMC + c * 4);
    }
    CP_COMMIT();

    // ---- S phase: 8 warps as 2m x 4n (32x32 warp tiles) ----
    const int wmS = (wid & 1) * 32;
    const int wnS = (wid >> 1) * 32;
    const uint32_t qa_lm = qb + (uint32_t)(((wmS + a_row) * QSTR + a_kof) * 4);
    const uint32_t kb_lm = (uint32_t)(((wnS + b_row) * KSTR + b_kof) * 4);
    for (int rc = 0; rc < 4; rc++) {
        CP_WAIT(0);
        __syncthreads();
        if (rc + 1 < 4) {
            uint32_t dstb = kb + (uint32_t)(((rc + 1) & 1) * 8704 * 4);
            const float* src = Kg + (size_t)(rc + 1) * 128 * DIMC;
#pragma unroll
            for (int i = 0; i < 8; i++) {
                int id = tid + i * 256;
                int r = id >> 4, c = id & 15;
                CP_ASYNC16(dstb + (uint32_t)((r * KSTR + c * 4) * 4), src + (size_t)r * DIMC + c * 4);
            }
            CP_COMMIT();
        }
        uint32_t ksm = kb + (uint32_t)((rc & 1) * 8704 * 4) + kb_lm;
        float acc[2][4][4];
#pragma unroll
        for (int mi = 0; mi < 2; mi++)
#pragma unroll
            for (int nj = 0; nj < 4; nj++)
#pragma unroll
                for (int q = 0; q < 4; q++) acc[mi][nj][q] = 0.f;

#pragma unroll
        for (int kk = 0; kk < 64; kk += 8) {
            uint32_t a[2][4], bb[4][2];
#pragma unroll
            for (int mi = 0; mi < 2; mi++)
                ldmx4(a[mi][0], a[mi][1], a[mi][2], a[mi][3],
                      qa_lm + (uint32_t)((mi * 16 * QSTR + kk) * 4));
#pragma unroll
            for (int njg = 0; njg < 4; njg += 2)
                ldmx4(bb[njg][0], bb[njg][1], bb[njg + 1][0], bb[njg + 1][1],
                      ksm + (uint32_t)((njg * 8 * KSTR + kk) * 4));
#pragma unroll
            for (int mi = 0; mi < 2; mi++)
#pragma unroll
                for (int nj = 0; nj < 4; nj++)
                    mma_tf32(acc[mi][nj], a[mi], bb[nj]);
        }
#pragma unroll
        for (int mi = 0; mi < 2; mi++) {
            int row = wmS + mi * 16 + g;
#pragma unroll
            for (int nj = 0; nj < 4; nj++) {
                int col = rc * 128 + wnS + nj * 8 + tg * 2;
                *(float2*)&Ss[row * SSTR + col]       = make_float2(acc[mi][nj][0], acc[mi][nj][1]);
                *(float2*)&Ss[(row + 8) * SSTR + col] = make_float2(acc[mi][nj][2], acc[mi][nj][3]);
            }
        }
    }
    __syncthreads();

    // ---- softmax: unnormalized tf32 exp; 1/sum deferred ----
    for (int r = wid; r < 64; r += 8) {
        float* row = Ss + r * SSTR;
        float m = -1e30f;
        for (int c = lane; c < 512; c += 32) m = fmaxf(m, row[c]);
#pragma unroll
        for (int o = 16; o > 0; o >>= 1) m = fmaxf(m, __shfl_xor_sync(0xffffffffu, m, o));
        float s = 0.f;
        for (int c = lane; c < 512; c += 32) {
            float e = tf32_rn(__expf(row[c] - m));
            row[c] = e;
            s += e;
        }
#pragma unroll
        for (int o = 16; o > 0; o >>= 1) s += __shfl_xor_sync(0xffffffffu, s, o);
        if (lane == 0) sInv[r] = 1.f / s;
    }

    // ---- PV phase: 8 warps as 4m x 2n (16x32 warp tiles) ----
    const int wmP = (wid & 3) * 16;
    const int wnP = (wid >> 2) * 32;
    const uint32_t sa_lm = sb + (uint32_t)(((wmP + a_row) * SSTR + a_kof) * 4);
    const uint32_t vb_lm = sb + (uint32_t)(KB_OFF * 4) +
                           (uint32_t)(((wnP + b_row) * VSTR + b_kof) * 4);
    float po[4][4];
#pragma unroll
    for (int nj = 0; nj < 4; nj++)
#pragma unroll
        for (int q = 0; q < 4; q++) po[nj][q] = 0.f;

    for (int rc = 0; rc < 4; rc++) {
        __syncthreads();
#pragma unroll
        for (int i = 0; i < 8; i++) {
            int id = tid + i * 256;
            int r = id & 127;
            int c = (id >> 7) * 4;
            float4 v = *(const float4*)(Vg + (size_t)(rc * 128 + r) * DIMC + c);
            KB[(c + 0) * VSTR + r] = v.x;
            KB[(c + 1) * VSTR + r] = v.y;
            KB[(c + 2) * VSTR + r] = v.z;
            KB[(c + 3) * VSTR + r] = v.w;
        }
        __syncthreads();
#pragma unroll
        for (int kk = 0; kk < 128; kk += 8) {
            uint32_t a[4], bb[4][2];
            ldmx4(a[0], a[1], a[2], a[3],
                  sa_lm + (uint32_t)((rc * 128 + kk) * 4));
#pragma unroll
            for (int njg = 0; njg < 4; njg += 2)
                ldmx4(bb[njg][0], bb[njg][1], bb[njg + 1][0], bb[njg + 1][1],
                      vb_lm + (uint32_t)((njg * 8 * VSTR + kk) * 4));
#pragma unroll
            for (int nj = 0; nj < 4; nj++)
                mma_tf32(po[nj], a, bb[nj]);
        }
    }

    // ---- epilogue: normalize (fp32), round to tf32, store ----
    float inv0 = sInv[wmP + g];
    float inv1 = sInv[wmP + g + 8];
    float* Og = g_O + ((size_t)(b * LC + q0 + wmP + g)) * DIMC + h * DHC + wnP;
#pragma unroll
    for (int nj = 0; nj < 4; nj++) {
        int col = nj * 8 + tg * 2;
        *(float2*)(Og + col) =
            make_float2(tf32_rn(po[nj][0] * inv0), tf32_rn(po[nj][1] * inv0));
        *(float2*)(Og + 8 * DIMC + col) =
            make_float2(tf32_rn(po[nj][2] * inv1), tf32_rn(po[nj][3] * inv1));
    }
}

// ---------------------------------------------------------------------------
// Launch
// ---------------------------------------------------------------------------
extern "C" void kernel_launch(void* const* d_in, const int* in_sizes, int n_in,
                              void* d_out, int out_size) {
    const float* x   = (const float*)d_in[0];
    const float* ctx = (const float*)d_in[1];
    const float* Wq  = (const float*)d_in[2];
    const float* Wk  = (const float*)d_in[3];
    const float* Wv  = (const float*)d_in[4];
    const float* Wo  = (const float*)d_in[5];
    float* out = (float*)d_out;

    void *pXr, *pCr, *pWqT, *pWkT, *pWvT, *pWoT, *pQ, *pK, *pV, *pO;
    cudaGetSymbolAddress(&pXr, g_Xr);
    cudaGetSymbolAddress(&pCr, g_Cr);
    cudaGetSymbolAddress(&pWqT, g_WqT);
    cudaGetSymbolAddress(&pWkT, g_WkT);
    cudaGetSymbolAddress(&pWvT, g_WvT);
    cudaGetSymbolAddress(&pWoT, g_WoT);
    cudaGetSymbolAddress(&pQ, g_Q);
    cudaGetSymbolAddress(&pK, g_K);
    cudaGetSymbolAddress(&pV, g_V);
    cudaGetSymbolAddress(&pO, g_O);

    cudaFuncSetAttribute(mma_gemm_kernel, cudaFuncAttributeMaxDynamicSharedMemorySize, GSM_TOTAL);
    cudaFuncSetAttribute(attn_mma_kernel, cudaFuncAttributeMaxDynamicSharedMemorySize, ATTN_SMEM);

    round_copy_kernel<<<(BC * LC * DIMC / 4 + 255) / 256, 256>>>(x,   (float*)pXr, BC * LC * DIMC / 4);   // 0
    round_copy_kernel<<<(BC * RC * DIMC / 4 + 255) / 256, 256>>>(ctx, (float*)pCr, BC * RC * DIMC / 4);   // 1
    dim3 tg3(DIMC / 32, DIMC / 32, 4);
    transpose_all_kernel<<<tg3, 256>>>(Wq, Wk, Wv, Wo,                                                     // 2
                                       (float*)pWqT, (float*)pWkT, (float*)pWvT, (float*)pWoT);

    mma_gemm_kernel<<<dim3(DIMC / 128, (BC * RC) / 128), 256, GSM_TOTAL>>>((const float*)pCr, (const float*)pWkT, (float*)pK, 1);  // 3
    mma_gemm_kernel<<<dim3(DIMC / 128, (BC * RC) / 128), 256, GSM_TOTAL>>>((const float*)pCr, (const float*)pWvT, (float*)pV, 1);  // 4
    mma_gemm_kernel<<<dim3(DIMC / 128, (BC * LC) / 128), 256, GSM_TOTAL>>>((const float*)pXr, (const float*)pWqT, (float*)pQ, 1);  // 5 <- ncu
    attn_mma_kernel<<<dim3(LC / 64, BC * HC), 256, ATTN_SMEM>>>();                                                                  // 6
    mma_gemm_kernel<<<dim3(DIMC / 128, (BC * LC) / 128), 256, GSM_TOTAL>>>((const float*)pO, (const float*)pWoT, out, 0);           // 7
}

// round 13
// speedup vs baseline: 1.3186x; 1.1058x over previous
#include <cuda_runtime.h>
#include <cstdint>
#include <math.h>

// Problem constants
#define DIMC 1024
#define HC   16
#define DHC  64
#define BC   4
#define LC   4096
#define RC   512
#define SCALEF 0.125f   // 64^-0.5

// ---------------------------------------------------------------------------
// Device-global scratch
// ---------------------------------------------------------------------------
__device__ float g_Q  [(size_t)BC * LC * DIMC];
__device__ float g_K  [(size_t)BC * RC * DIMC];
__device__ float g_V  [(size_t)BC * RC * DIMC];
__device__ float g_O  [(size_t)BC * LC * DIMC];
__device__ float g_Xr [(size_t)BC * LC * DIMC];
__device__ float g_Cr [(size_t)BC * RC * DIMC];
__device__ float g_WqT [(size_t)DIMC * DIMC];
__device__ float g_WkvT[(size_t)2 * DIMC * DIMC];   // rows 0-1023: Wk^T, 1024-2047: Wv^T
__device__ float g_WoT [(size_t)DIMC * DIMC];

// ---------------------------------------------------------------------------
// Helpers
// ---------------------------------------------------------------------------
__device__ __forceinline__ uint32_t smem_u32(const void* p) {
    uint32_t a;
    asm("{ .reg .u64 t; cvta.to.shared.u64 t, %1; cvt.u32.u64 %0, t; }" : "=r"(a) : "l"(p));
    return a;
}
__device__ __forceinline__ float tf32_rn(float x) {
    float y;
    asm("cvt.rna.tf32.f32 %0, %1;" : "=f"(y) : "f"(x));
    return y;
}

#define CP_ASYNC16(dst, src) \
    asm volatile("cp.async.cg.shared.global [%0], [%1], 16;" :: "r"(dst), "l"(src) : "memory")
#define CP_COMMIT() asm volatile("cp.async.commit_group;" ::: "memory")
#define CP_WAIT(n)  asm volatile("cp.async.wait_group %0;" :: "n"(n) : "memory")

__device__ __forceinline__ void mma_tf32(float* c, const uint32_t* a, const uint32_t* b) {
    asm volatile(
        "mma.sync.aligned.m16n8k8.row.col.f32.tf32.tf32.f32 "
        "{%0,%1,%2,%3}, {%4,%5,%6,%7}, {%8,%9}, {%0,%1,%2,%3};"
        : "+f"(c[0]), "+f"(c[1]), "+f"(c[2]), "+f"(c[3])
        : "r"(a[0]), "r"(a[1]), "r"(a[2]), "r"(a[3]), "r"(b[0]), "r"(b[1]));
}

__device__ __forceinline__ void ldmx4(uint32_t& r0, uint32_t& r1, uint32_t& r2, uint32_t& r3,
                                      uint32_t addr) {
    asm volatile("ldmatrix.sync.aligned.m8n8.x4.shared.b16 {%0,%1,%2,%3}, [%4];"
                 : "=r"(r0), "=r"(r1), "=r"(r2), "=r"(r3) : "r"(addr));
}

// ---------------------------------------------------------------------------
// Preprocessing kernels
// ---------------------------------------------------------------------------
__global__ __launch_bounds__(256) void round_copy_kernel(const float* __restrict__ src,
                                                         float* __restrict__ dst, int n4) {
    int i = blockIdx.x * 256 + threadIdx.x;
    if (i < n4) {
        float4 v = ((const float4*)src)[i];
        v.x = tf32_rn(v.x); v.y = tf32_rn(v.y); v.z = tf32_rn(v.z); v.w = tf32_rn(v.w);
        ((float4*)dst)[i] = v;
    }
}

__global__ __launch_bounds__(256) void transpose_all_kernel(const float* __restrict__ W0,
                                                            const float* __restrict__ W1,
                                                            const float* __restrict__ W2,
                                                            const float* __restrict__ W3,
                                                            float* __restrict__ T0,
                                                            float* __restrict__ T1,
                                                            float* __restrict__ T2,
                                                            float* __restrict__ T3) {
    __shared__ float t[32][33];
    const float* W;
    float* Wt;
    float scale = 1.0f;
    switch (blockIdx.z) {
        case 0: W = W0; Wt = T0; scale = SCALEF; break;
        case 1: W = W1; Wt = T1; break;
        case 2: W = W2; Wt = T2; break;
        default: W = W3; Wt = T3; break;
    }
    int tx = threadIdx.x & 31;
    int ty = threadIdx.x >> 5;
    int x = blockIdx.x * 32 + tx;
#pragma unroll
    for (int i = ty; i < 32; i += 8) {
        int y = blockIdx.y * 32 + i;
        t[i][tx] = tf32_rn(W[(size_t)y * DIMC + x] * scale);
    }
    __syncthreads();
    int xo = blockIdx.y * 32 + tx;
#pragma unroll
    for (int i = ty; i < 32; i += 8) {
        int yo = blockIdx.x * 32 + i;
        Wt[(size_t)yo * DIMC + xo] = t[tx][i];
    }
}

// ---------------------------------------------------------------------------
// tf32 mma.sync GEMM: 128x128 CTA tile, BK=32, XOR-swizzled smem (128B rows),
// 3-stage cp.async, ldmatrix frags, 2 CTAs/SM.
// Output column-split: cols [0,nsplit) -> C, [nsplit,..) -> C2 (KV fusion).
// ---------------------------------------------------------------------------
#define BK 32
#define TILE_BYTES (128 * 128)               // one 128-row x 128B tile
#define STG_BYTES  (2 * TILE_BYTES)          // A + B per stage
#define GSM_TOTAL  (3 * STG_BYTES)           // 98304 B

__device__ __forceinline__ void load_stage(uint32_t sbase, const float* __restrict__ Ab,
                                           const float* __restrict__ Bb, int kt, int tid) {
    uint32_t sA = sbase;
    uint32_t sB = sbase + TILE_BYTES;
    const float* As_ = Ab + kt * BK;
    const float* Bs_ = Bb + kt * BK;
#pragma unroll
    for (int i = 0; i < 4; i++) {
        int id = tid + i * 256;            // 0..1023
        int r = id >> 3;                   // 0..127
        int gr = id & 7;                   // granule
        uint32_t off = (uint32_t)(r * 128 + ((gr ^ (r & 7)) << 4));
        CP_ASYNC16(sA + off, As_ + (size_t)r * DIMC + gr * 4);
        CP_ASYNC16(sB + off, Bs_ + (size_t)r * DIMC + gr * 4);
    }
}

__global__ __launch_bounds__(256, 2) void mma_gemm_kernel(const float* __restrict__ A,
                                                          const float* __restrict__ Bt,
                                                          float* __restrict__ C,
                                                          float* __restrict__ C2,
                                                          int nsplit,
                                                          int round_out) {
    extern __shared__ float sm[];
    const int tid = threadIdx.x;
    const int lane = tid & 31;
    const int g = lane >> 2;
    const int tg = lane & 3;
    const int wid = tid >> 5;
    const int wm = (wid & 3) * 32;
    const int wn = (wid >> 2) * 64;

    // ldmatrix lane mapping
    const int a_row = (lane & 7) + ((lane >> 3) & 1) * 8;
    const int a_g   = lane >> 4;           // granule offset within frag
    const int b_row = (lane & 7) + (lane >> 4) * 8;
    const int b_g   = (lane >> 3) & 1;

    const float* Ab = A  + (size_t)blockIdx.y * 128 * DIMC;
    const float* Bb = Bt + (size_t)blockIdx.x * 128 * DIMC;
    uint32_t sb = smem_u32(sm);

    // Precompute per-lane swizzle row bases
    uint32_t aBase[2], bBase[4];
    int aX[2], bX[4];
#pragma unroll
    for (int mi = 0; mi < 2; mi++) {
        int R = wm + a_row + mi * 16;
        aBase[mi] = (uint32_t)(R * 128);
        aX[mi] = R & 7;
    }
#pragma unroll
    for (int j = 0; j < 4; j++) {
        int R = wn + b_row + j * 16;
        bBase[j] = (uint32_t)(TILE_BYTES + R * 128);
        bX[j] = R & 7;
    }

    float acc[2][8][4];
#pragma unroll
    for (int mi = 0; mi < 2; mi++)
#pragma unroll
        for (int nj = 0; nj < 8; nj++)
#pragma unroll
            for (int q = 0; q < 4; q++) acc[mi][nj][q] = 0.f;

    load_stage(sb + 0 * STG_BYTES, Ab, Bb, 0, tid); CP_COMMIT();
    load_stage(sb + 1 * STG_BYTES, Ab, Bb, 1, tid); CP_COMMIT();

    const int NKT = DIMC / BK;   // 32
    for (int kt = 0; kt < NKT; kt++) {
        if (kt < NKT - 1) { CP_WAIT(1); } else { CP_WAIT(0); }
        __syncthreads();

        uint32_t stg = sb + (uint32_t)((kt % 3) * STG_BYTES);

#pragma unroll
        for (int kk = 0; kk < BK; kk += 8) {
            int Ga = (kk >> 2) + a_g;
            int Gb = (kk >> 2) + b_g;
            uint32_t a[2][4], b[8][2];
#pragma unroll
            for (int mi = 0; mi < 2; mi++)
                ldmx4(a[mi][0], a[mi][1], a[mi][2], a[mi][3],
                      stg + aBase[mi] + (uint32_t)((Ga ^ aX[mi]) << 4));
#pragma unroll
            for (int j = 0; j < 4; j++)
                ldmx4(b[2 * j][0], b[2 * j][1], b[2 * j + 1][0], b[2 * j + 1][1],
                      stg + bBase[j] + (uint32_t)((Gb ^ bX[j]) << 4));
#pragma unroll
            for (int mi = 0; mi < 2; mi++)
#pragma unroll
                for (int nj = 0; nj < 8; nj++)
                    mma_tf32(acc[mi][nj], a[mi], b[nj]);
        }

        if (kt + 2 < NKT) {
            load_stage(sb + (uint32_t)(((kt + 2) % 3) * STG_BYTES), Ab, Bb, kt + 2, tid);
            CP_COMMIT();
        }
    }

    if (round_out) {
#pragma unroll
        for (int mi = 0; mi < 2; mi++)
#pragma unroll
            for (int nj = 0; nj < 8; nj++)
#pragma unroll
                for (int q = 0; q < 4; q++) acc[mi][nj][q] = tf32_rn(acc[mi][nj][q]);
    }

    // Output routing (KV fusion): columns >= nsplit go to C2
    int colb = blockIdx.x * 128;
    float* Cout = C;
    if (colb >= nsplit) { Cout = C2; colb -= nsplit; }

    size_t rowb = (size_t)blockIdx.y * 128 + wm + g;
#pragma unroll
    for (int mi = 0; mi < 2; mi++) {
        float* C0 = Cout + (rowb + mi * 16) * DIMC + colb + wn;
        float* C1 = C0 + 8 * DIMC;
#pragma unroll
        for (int nj = 0; nj < 8; nj++) {
            *(float2*)(C0 + nj * 8 + tg * 2) = make_float2(acc[mi][nj][0], acc[mi][nj][1]);
            *(float2*)(C1 + nj * 8 + tg * 2) = make_float2(acc[mi][nj][2], acc[mi][nj][3]);
        }
    }
}

// ---------------------------------------------------------------------------
// Tensor-core attention (ldmatrix frags): one CTA = (b,h) x 64 q rows.
// (unchanged from R11)
// ---------------------------------------------------------------------------
#define SSTR 516
#define QSTR 68
#define KSTR 68
#define VSTR 132
#define S_OFF   0
#define Q_OFF   33024
#define KB_OFF  37376
#define INV_OFF 54784
#define ATTN_SMEM ((INV_OFF + 64) * 4)   // 219,392 B

__global__ __launch_bounds__(256) void attn_mma_kernel() {
    extern __shared__ float sm[];
    float* Ss = sm + S_OFF;
    float* KB = sm + KB_OFF;
    float* sInv = sm + INV_OFF;
    uint32_t sb = smem_u32(sm);
    const uint32_t qb = sb + Q_OFF * 4;
    const uint32_t kb = sb + KB_OFF * 4;

    const int tid = threadIdx.x;
    const int lane = tid & 31;
    const int g = lane >> 2;
    const int tg = lane & 3;
    const int wid = tid >> 5;
    const int bh = blockIdx.y;
    const int b = bh >> 4;
    const int h = bh & 15;
    const int q0 = blockIdx.x * 64;

    const int a_row = (lane & 7) + ((lane >> 3) & 1) * 8;
    const int a_kof = (lane >> 4) * 4;
    const int b_row = (lane & 7) + (lane >> 4) * 8;
    const int b_kof = ((lane >> 3) & 1) * 4;

    const float* Qg = g_Q + ((size_t)(b * LC + q0)) * DIMC + h * DHC;
    const float* Kg = g_K + ((size_t)(b * RC)) * DIMC + h * DHC;
    const float* Vg = g_V + ((size_t)(b * RC)) * DIMC + h * DHC;

#pragma unroll
    for (int i = 0; i < 4; i++) {
        int id = tid + i * 256;
        int r = id >> 4, c = id & 15;
        CP_ASYNC16(qb + (uint32_t)((r * QSTR + c * 4) * 4), Qg + (size_t)r * DIMC + c * 4);
    }
#pragma unroll
    for (int i = 0; i < 8; i++) {
        int id = tid + i * 256;
        int r = id >> 4, c = id & 15;
        CP_ASYNC16(kb + (uint32_t)((r * KSTR + c * 4) * 4), Kg + (size_t)r * DIMC + c * 4);
    }
    CP_COMMIT();

    const int wmS = (wid & 1) * 32;
    const int wnS = (wid >> 1) * 32;
    const uint32_t qa_lm = qb + (uint32_t)(((wmS + a_row) * QSTR + a_kof) * 4);
    const uint32_t kb_lm = (uint32_t)(((wnS + b_row) * KSTR + b_kof) * 4);
    for (int rc = 0; rc < 4; rc++) {
        CP_WAIT(0);
        __syncthreads();
        if (rc + 1 < 4) {
            uint32_t dstb = kb + (uint32_t)(((rc + 1) & 1) * 8704 * 4);
            const float* src = Kg + (size_t)(rc + 1) * 128 * DIMC;
#pragma unroll
            for (int i = 0; i < 8; i++) {
                int id = tid + i * 256;
                int r = id >> 4, c = id & 15;
                CP_ASYNC16(dstb + (uint32_t)((r * KSTR + c * 4) * 4), src + (size_t)r * DIMC + c * 4);
            }
            CP_COMMIT();
        }
        uint32_t ksm = kb + (uint32_t)((rc & 1) * 8704 * 4) + kb_lm;
        float acc[2][4][4];
#pragma unroll
        for (int mi = 0; mi < 2; mi++)
#pragma unroll
            for (int nj = 0; nj < 4; nj++)
#pragma unroll
                for (int q = 0; q < 4; q++) acc[mi][nj][q] = 0.f;

#pragma unroll
        for (int kk = 0; kk < 64; kk += 8) {
            uint32_t a[2][4], bb[4][2];
#pragma unroll
            for (int mi = 0; mi < 2; mi++)
                ldmx4(a[mi][0], a[mi][1], a[mi][2], a[mi][3],
                      qa_lm + (uint32_t)((mi * 16 * QSTR + kk) * 4));
#pragma unroll
            for (int njg = 0; njg < 4; njg += 2)
                ldmx4(bb[njg][0], bb[njg][1], bb[njg + 1][0], bb[njg + 1][1],
                      ksm + (uint32_t)((njg * 8 * KSTR + kk) * 4));
#pragma unroll
            for (int mi = 0; mi < 2; mi++)
#pragma unroll
                for (int nj = 0; nj < 4; nj++)
                    mma_tf32(acc[mi][nj], a[mi], bb[nj]);
        }
#pragma unroll
        for (int mi = 0; mi < 2; mi++) {
            int row = wmS + mi * 16 + g;
#pragma unroll
            for (int nj = 0; nj < 4; nj++) {
                int col = rc * 128 + wnS + nj * 8 + tg * 2;
                *(float2*)&Ss[row * SSTR + col]       = make_float2(acc[mi][nj][0], acc[mi][nj][1]);
                *(float2*)&Ss[(row + 8) * SSTR + col] = make_float2(acc[mi][nj][2], acc[mi][nj][3]);
            }
        }
    }
    __syncthreads();

    for (int r = wid; r < 64; r += 8) {
        float* row = Ss + r * SSTR;
        float m = -1e30f;
        for (int c = lane; c < 512; c += 32) m = fmaxf(m, row[c]);
#pragma unroll
        for (int o = 16; o > 0; o >>= 1) m = fmaxf(m, __shfl_xor_sync(0xffffffffu, m, o));
        float s = 0.f;
        for (int c = lane; c < 512; c += 32) {
            float e = tf32_rn(__expf(row[c] - m));
            row[c] = e;
            s += e;
        }
#pragma unroll
        for (int o = 16; o > 0; o >>= 1) s += __shfl_xor_sync(0xffffffffu, s, o);
        if (lane == 0) sInv[r] = 1.f / s;
    }

    const int wmP = (wid & 3) * 16;
    const int wnP = (wid >> 2) * 32;
    const uint32_t sa_lm = sb + (uint32_t)(((wmP + a_row) * SSTR + a_kof) * 4);
    const uint32_t vb_lm = sb + (uint32_t)(KB_OFF * 4) +
                           (uint32_t)(((wnP + b_row) * VSTR + b_kof) * 4);
    float po[4][4];
#pragma unroll
    for (int nj = 0; nj < 4; nj++)
#pragma unroll
        for (int q = 0; q < 4; q++) po[nj][q] = 0.f;

    for (int rc = 0; rc < 4; rc++) {
        __syncthreads();
#pragma unroll
        for (int i = 0; i < 8; i++) {
            int id = tid + i * 256;
            int r = id & 127;
            int c = (id >> 7) * 4;
            float4 v = *(const float4*)(Vg + (size_t)(rc * 128 + r) * DIMC + c);
            KB[(c + 0) * VSTR + r] = v.x;
            KB[(c + 1) * VSTR + r] = v.y;
            KB[(c + 2) * VSTR + r] = v.z;
            KB[(c + 3) * VSTR + r] = v.w;
        }
        __syncthreads();
#pragma unroll
        for (int kk = 0; kk < 128; kk += 8) {
            uint32_t a[4], bb[4][2];
            ldmx4(a[0], a[1], a[2], a[3],
                  sa_lm + (uint32_t)((rc * 128 + kk) * 4));
#pragma unroll
            for (int njg = 0; njg < 4; njg += 2)
                ldmx4(bb[njg][0], bb[njg][1], bb[njg + 1][0], bb[njg + 1][1],
                      vb_lm + (uint32_t)((njg * 8 * VSTR + kk) * 4));
#pragma unroll
            for (int nj = 0; nj < 4; nj++)
                mma_tf32(po[nj], a, bb[nj]);
        }
    }

    float inv0 = sInv[wmP + g];
    float inv1 = sInv[wmP + g + 8];
    float* Og = g_O + ((size_t)(b * LC + q0 + wmP + g)) * DIMC + h * DHC + wnP;
#pragma unroll
    for (int nj = 0; nj < 4; nj++) {
        int col = nj * 8 + tg * 2;
        *(float2*)(Og + col) =
            make_float2(tf32_rn(po[nj][0] * inv0), tf32_rn(po[nj][1] * inv0));
        *(float2*)(Og + 8 * DIMC + col) =
            make_float2(tf32_rn(po[nj][2] * inv1), tf32_rn(po[nj][3] * inv1));
    }
}

// ---------------------------------------------------------------------------
// Launch
// ---------------------------------------------------------------------------
extern "C" void kernel_launch(void* const* d_in, const int* in_sizes, int n_in,
                              void* d_out, int out_size) {
    const float* x   = (const float*)d_in[0];
    const float* ctx = (const float*)d_in[1];
    const float* Wq  = (const float*)d_in[2];
    const float* Wk  = (const float*)d_in[3];
    const float* Wv  = (const float*)d_in[4];
    const float* Wo  = (const float*)d_in[5];
    float* out = (float*)d_out;

    void *pXr, *pCr, *pWqT, *pWkvT, *pWoT, *pQ, *pK, *pV, *pO;
    cudaGetSymbolAddress(&pXr, g_Xr);
    cudaGetSymbolAddress(&pCr, g_Cr);
    cudaGetSymbolAddress(&pWqT, g_WqT);
    cudaGetSymbolAddress(&pWkvT, g_WkvT);
    cudaGetSymbolAddress(&pWoT, g_WoT);
    cudaGetSymbolAddress(&pQ, g_Q);
    cudaGetSymbolAddress(&pK, g_K);
    cudaGetSymbolAddress(&pV, g_V);
    cudaGetSymbolAddress(&pO, g_O);

    float* WkvT0 = (float*)pWkvT;
    float* WkvT1 = (float*)pWkvT + (size_t)DIMC * DIMC;

    cudaFuncSetAttribute(mma_gemm_kernel, cudaFuncAttributeMaxDynamicSharedMemorySize, GSM_TOTAL);
    cudaFuncSetAttribute(attn_mma_kernel, cudaFuncAttributeMaxDynamicSharedMemorySize, ATTN_SMEM);

    round_copy_kernel<<<(BC * LC * DIMC / 4 + 255) / 256, 256>>>(x,   (float*)pXr, BC * LC * DIMC / 4);   // 0
    round_copy_kernel<<<(BC * RC * DIMC / 4 + 255) / 256, 256>>>(ctx, (float*)pCr, BC * RC * DIMC / 4);   // 1
    dim3 tg3(DIMC / 32, DIMC / 32, 4);
    transpose_all_kernel<<<tg3, 256>>>(Wq, Wk, Wv, Wo,                                                     // 2
                                       (float*)pWqT, WkvT0, WkvT1, (float*)pWoT);

    // 3: fused K+V projection (N = 2048, split at 1024)
    mma_gemm_kernel<<<dim3(2 * DIMC / 128, (BC * RC) / 128), 256, GSM_TOTAL>>>(
        (const float*)pCr, (const float*)pWkvT, (float*)pK, (float*)pV, DIMC, 1);
    // 4: Q projection
    mma_gemm_kernel<<<dim3(DIMC / 128, (BC * LC) / 128), 256, GSM_TOTAL>>>(
        (const float*)pXr, (const float*)pWqT, (float*)pQ, (float*)pQ, 1 << 30, 1);
    // 5: attention  <- ncu -s 5 profiles this
    attn_mma_kernel<<<dim3(LC / 64, BC * HC), 256, ATTN_SMEM>>>();
    // 6: output projection
    mma_gemm_kernel<<<dim3(DIMC / 128, (BC * LC) / 128), 256, GSM_TOTAL>>>(
        (const float*)pO, (const float*)pWoT, out, out, 1 << 30, 0);
}

// round 14
// speedup vs baseline: 1.5897x; 1.2056x over previous
#include <cuda_runtime.h>
#include <cuda_fp16.h>
#include <cstdint>
#include <math.h>

// Problem constants
#define DIMC 1024
#define HC   16
#define DHC  64
#define BC   4
#define LC   4096
#define RC   512
#define SCALEF 0.125f   // 64^-0.5

// ---------------------------------------------------------------------------
// Device-global scratch
// ---------------------------------------------------------------------------
__device__ float  g_Q  [(size_t)BC * LC * DIMC];   // fp32 (tf32-rounded) for attention
__device__ float  g_K  [(size_t)BC * RC * DIMC];
__device__ float  g_V  [(size_t)BC * RC * DIMC];
__device__ __half g_Oh [(size_t)BC * LC * DIMC];   // attention out, fp16 (feeds O-proj)
__device__ __half g_Xr [(size_t)BC * LC * DIMC];   // x rounded to fp16
__device__ __half g_Cr [(size_t)BC * RC * DIMC];
__device__ __half g_WqT [(size_t)DIMC * DIMC];     // W^T, fp16 (Wq pre-scaled)
__device__ __half g_WkvT[(size_t)2 * DIMC * DIMC]; // rows 0-1023 Wk^T, 1024-2047 Wv^T
__device__ __half g_WoT [(size_t)DIMC * DIMC];

// ---------------------------------------------------------------------------
// Helpers
// ---------------------------------------------------------------------------
__device__ __forceinline__ uint32_t smem_u32(const void* p) {
    uint32_t a;
    asm("{ .reg .u64 t; cvta.to.shared.u64 t, %1; cvt.u32.u64 %0, t; }" : "=r"(a) : "l"(p));
    return a;
}
__device__ __forceinline__ float tf32_rn(float x) {
    float y;
    asm("cvt.rna.tf32.f32 %0, %1;" : "=f"(y) : "f"(x));
    return y;
}

#define CP_ASYNC16(dst, src) \
    asm volatile("cp.async.cg.shared.global [%0], [%1], 16;" :: "r"(dst), "l"(src) : "memory")
#define CP_COMMIT() asm volatile("cp.async.commit_group;" ::: "memory")
#define CP_WAIT(n)  asm volatile("cp.async.wait_group %0;" :: "n"(n) : "memory")

// fp16 mma: m16n8k16, fp32 accumulate
__device__ __forceinline__ void mma_f16(float* c, const uint32_t* a, const uint32_t* b) {
    asm volatile(
        "mma.sync.aligned.m16n8k16.row.col.f32.f16.f16.f32 "
        "{%0,%1,%2,%3}, {%4,%5,%6,%7}, {%8,%9}, {%0,%1,%2,%3};"
        : "+f"(c[0]), "+f"(c[1]), "+f"(c[2]), "+f"(c[3])
        : "r"(a[0]), "r"(a[1]), "r"(a[2]), "r"(a[3]), "r"(b[0]), "r"(b[1]));
}
// tf32 mma (attention, unchanged)
__device__ __forceinline__ void mma_tf32(float* c, const uint32_t* a, const uint32_t* b) {
    asm volatile(
        "mma.sync.aligned.m16n8k8.row.col.f32.tf32.tf32.f32 "
        "{%0,%1,%2,%3}, {%4,%5,%6,%7}, {%8,%9}, {%0,%1,%2,%3};"
        : "+f"(c[0]), "+f"(c[1]), "+f"(c[2]), "+f"(c[3])
        : "r"(a[0]), "r"(a[1]), "r"(a[2]), "r"(a[3]), "r"(b[0]), "r"(b[1]));
}

__device__ __forceinline__ void ldmx4(uint32_t& r0, uint32_t& r1, uint32_t& r2, uint32_t& r3,
                                      uint32_t addr) {
    asm volatile("ldmatrix.sync.aligned.m8n8.x4.shared.b16 {%0,%1,%2,%3}, [%4];"
                 : "=r"(r0), "=r"(r1), "=r"(r2), "=r"(r3) : "r"(addr));
}

// ---------------------------------------------------------------------------
// Preprocessing kernels (fp32 -> fp16)
// ---------------------------------------------------------------------------
__global__ __launch_bounds__(256) void round_copy_h_kernel(const float* __restrict__ src,
                                                           __half* __restrict__ dst, int n4) {
    int i = blockIdx.x * 256 + threadIdx.x;
    if (i < n4) {
        float4 v = ((const float4*)src)[i];
        __half2 h0 = __floats2half2_rn(v.x, v.y);
        __half2 h1 = __floats2half2_rn(v.z, v.w);
        ((__half2*)dst)[2 * i]     = h0;
        ((__half2*)dst)[2 * i + 1] = h1;
    }
}

__global__ __launch_bounds__(256) void transpose_all_kernel(const float* __restrict__ W0,
                                                            const float* __restrict__ W1,
                                                            const float* __restrict__ W2,
                                                            const float* __restrict__ W3,
                                                            __half* __restrict__ T0,
                                                            __half* __restrict__ T1,
                                                            __half* __restrict__ T2,
                                                            __half* __restrict__ T3) {
    __shared__ float t[32][33];
    const float* W;
    __half* Wt;
    float scale = 1.0f;
    switch (blockIdx.z) {
        case 0: W = W0; Wt = T0; scale = SCALEF; break;
        case 1: W = W1; Wt = T1; break;
        case 2: W = W2; Wt = T2; break;
        default: W = W3; Wt = T3; break;
    }
    int tx = threadIdx.x & 31;
    int ty = threadIdx.x >> 5;
    int x = blockIdx.x * 32 + tx;
#pragma unroll
    for (int i = ty; i < 32; i += 8) {
        int y = blockIdx.y * 32 + i;
        t[i][tx] = W[(size_t)y * DIMC + x] * scale;
    }
    __syncthreads();
    int xo = blockIdx.y * 32 + tx;
#pragma unroll
    for (int i = ty; i < 32; i += 8) {
        int yo = blockIdx.x * 32 + i;
        Wt[(size_t)yo * DIMC + xo] = __float2half_rn(t[tx][i]);
    }
}

// ---------------------------------------------------------------------------
// fp16 mma.sync GEMM: 128x128 CTA tile, BK=64 halfs (128B swizzled rows),
// 3-stage cp.async, ldmatrix frags, 2 CTAs/SM.
// C[M,N] = A[M,1024] @ Bt[N,1024]^T; column-split output (KV fusion).
// round_out=1 -> tf32-rounded fp32 C (Q/K/V for tf32 attention).
// ---------------------------------------------------------------------------
#define BKH 64
#define TILE_BYTES (128 * 128)               // 16KB (128 rows x 128B)
#define STG_BYTES  (2 * TILE_BYTES)          // 32KB
#define GSM_TOTAL  (3 * STG_BYTES)           // 98304 B

__device__ __forceinline__ void load_stage(uint32_t sbase, const __half* __restrict__ Ab,
                                           const __half* __restrict__ Bb, int kt, int tid) {
    uint32_t sA = sbase;
    uint32_t sB = sbase + TILE_BYTES;
    const __half* As_ = Ab + kt * BKH;
    const __half* Bs_ = Bb + kt * BKH;
#pragma unroll
    for (int i = 0; i < 4; i++) {
        int id = tid + i * 256;            // 0..1023
        int r = id >> 3;                   // 0..127
        int gr = id & 7;                   // 16B granule (8 halfs)
        uint32_t off = (uint32_t)(r * 128 + ((gr ^ (r & 7)) << 4));
        CP_ASYNC16(sA + off, As_ + (size_t)r * DIMC + gr * 8);
        CP_ASYNC16(sB + off, Bs_ + (size_t)r * DIMC + gr * 8);
    }
}

__global__ __launch_bounds__(256, 2) void mma_gemm_kernel(const __half* __restrict__ A,
                                                          const __half* __restrict__ Bt,
                                                          float* __restrict__ C,
                                                          float* __restrict__ C2,
                                                          int nsplit,
                                                          int round_out) {
    extern __shared__ float sm[];
    const int tid = threadIdx.x;
    const int lane = tid & 31;
    const int g = lane >> 2;
    const int tg = lane & 3;
    const int wid = tid >> 5;
    const int wm = (wid & 3) * 32;
    const int wn = (wid >> 2) * 64;

    const int a_row = (lane & 7) + ((lane >> 3) & 1) * 8;
    const int a_g   = lane >> 4;           // k granule hi/lo
    const int b_row = (lane & 7) + (lane >> 4) * 8;
    const int b_g   = (lane >> 3) & 1;

    const __half* Ab = A  + (size_t)blockIdx.y * 128 * DIMC;
    const __half* Bb = Bt + (size_t)blockIdx.x * 128 * DIMC;
    uint32_t sb = smem_u32(sm);

    uint32_t aBase[2], bBase[4];
    int aX[2], bX[4];
#pragma unroll
    for (int mi = 0; mi < 2; mi++) {
        int R = wm + a_row + mi * 16;
        aBase[mi] = (uint32_t)(R * 128);
        aX[mi] = R & 7;
    }
#pragma unroll
    for (int j = 0; j < 4; j++) {
        int R = wn + b_row + j * 16;
        bBase[j] = (uint32_t)(TILE_BYTES + R * 128);
        bX[j] = R & 7;
    }

    float acc[2][8][4];
#pragma unroll
    for (int mi = 0; mi < 2; mi++)
#pragma unroll
        for (int nj = 0; nj < 8; nj++)
#pragma unroll
            for (int q = 0; q < 4; q++) acc[mi][nj][q] = 0.f;

    load_stage(sb + 0 * STG_BYTES, Ab, Bb, 0, tid); CP_COMMIT();
    load_stage(sb + 1 * STG_BYTES, Ab, Bb, 1, tid); CP_COMMIT();

    const int NKT = DIMC / BKH;   // 16
    for (int kt = 0; kt < NKT; kt++) {
        if (kt < NKT - 1) { CP_WAIT(1); } else { CP_WAIT(0); }
        __syncthreads();

        uint32_t stg = sb + (uint32_t)((kt % 3) * STG_BYTES);

#pragma unroll
        for (int kk = 0; kk < BKH; kk += 16) {
            int Ga = (kk >> 3) + a_g;
            int Gb = (kk >> 3) + b_g;
            uint32_t a[2][4], b[8][2];
#pragma unroll
            for (int mi = 0; mi < 2; mi++)
                ldmx4(a[mi][0], a[mi][1], a[mi][2], a[mi][3],
                      stg + aBase[mi] + (uint32_t)((Ga ^ aX[mi]) << 4));
#pragma unroll
            for (int j = 0; j < 4; j++)
                ldmx4(b[2 * j][0], b[2 * j][1], b[2 * j + 1][0], b[2 * j + 1][1],
                      stg + bBase[j] + (uint32_t)((Gb ^ bX[j]) << 4));
#pragma unroll
            for (int mi = 0; mi < 2; mi++)
#pragma unroll
                for (int nj = 0; nj < 8; nj++)
                    mma_f16(acc[mi][nj], a[mi], b[nj]);
        }

        if (kt + 2 < NKT) {
            load_stage(sb + (uint32_t)(((kt + 2) % 3) * STG_BYTES), Ab, Bb, kt + 2, tid);
            CP_COMMIT();
        }
    }

    if (round_out) {
#pragma unroll
        for (int mi = 0; mi < 2; mi++)
#pragma unroll
            for (int nj = 0; nj < 8; nj++)
#pragma unroll
                for (int q = 0; q < 4; q++) acc[mi][nj][q] = tf32_rn(acc[mi][nj][q]);
    }

    int colb = blockIdx.x * 128;
    float* Cout = C;
    if (colb >= nsplit) { Cout = C2; colb -= nsplit; }

    size_t rowb = (size_t)blockIdx.y * 128 + wm + g;
#pragma unroll
    for (int mi = 0; mi < 2; mi++) {
        float* C0 = Cout + (rowb + mi * 16) * DIMC + colb + wn;
        float* C1 = C0 + 8 * DIMC;
#pragma unroll
        for (int nj = 0; nj < 8; nj++) {
            *(float2*)(C0 + nj * 8 + tg * 2) = make_float2(acc[mi][nj][0], acc[mi][nj][1]);
            *(float2*)(C1 + nj * 8 + tg * 2) = make_float2(acc[mi][nj][2], acc[mi][nj][3]);
        }
    }
}

// ---------------------------------------------------------------------------
// Tensor-core attention (tf32, unchanged from R13 except fp16 output store)
// ---------------------------------------------------------------------------
#define SSTR 516
#define QSTR 68
#define KSTR 68
#define VSTR 132
#define S_OFF   0
#define Q_OFF   33024
#define KB_OFF  37376
#define INV_OFF 54784
#define ATTN_SMEM ((INV_OFF + 64) * 4)   // 219,392 B

__global__ __launch_bounds__(256) void attn_mma_kernel() {
    extern __shared__ float sm[];
    float* Ss = sm + S_OFF;
    float* KB = sm + KB_OFF;
    float* sInv = sm + INV_OFF;
    uint32_t sb = smem_u32(sm);
    const uint32_t qb = sb + Q_OFF * 4;
    const uint32_t kb = sb + KB_OFF * 4;

    const int tid = threadIdx.x;
    const int lane = tid & 31;
    const int g = lane >> 2;
    const int tg = lane & 3;
    const int wid = tid >> 5;
    const int bh = blockIdx.y;
    const int b = bh >> 4;
    const int h = bh & 15;
    const int q0 = blockIdx.x * 64;

    const int a_row = (lane & 7) + ((lane >> 3) & 1) * 8;
    const int a_kof = (lane >> 4) * 4;
    const int b_row = (lane & 7) + (lane >> 4) * 8;
    const int b_kof = ((lane >> 3) & 1) * 4;

    const float* Qg = g_Q + ((size_t)(b * LC + q0)) * DIMC + h * DHC;
    const float* Kg = g_K + ((size_t)(b * RC)) * DIMC + h * DHC;
    const float* Vg = g_V + ((size_t)(b * RC)) * DIMC + h * DHC;

#pragma unroll
    for (int i = 0; i < 4; i++) {
        int id = tid + i * 256;
        int r = id >> 4, c = id & 15;
        CP_ASYNC16(qb + (uint32_t)((r * QSTR + c * 4) * 4), Qg + (size_t)r * DIMC + c * 4);
    }
#pragma unroll
    for (int i = 0; i < 8; i++) {
        int id = tid + i * 256;
        int r = id >> 4, c = id & 15;
        CP_ASYNC16(kb + (uint32_t)((r * KSTR + c * 4) * 4), Kg + (size_t)r * DIMC + c * 4);
    }
    CP_COMMIT();

    const int wmS = (wid & 1) * 32;
    const int wnS = (wid >> 1) * 32;
    const uint32_t qa_lm = qb + (uint32_t)(((wmS + a_row) * QSTR + a_kof) * 4);
    const uint32_t kb_lm = (uint32_t)(((wnS + b_row) * KSTR + b_kof) * 4);
    for (int rc = 0; rc < 4; rc++) {
        CP_WAIT(0);
        __syncthreads();
        if (rc + 1 < 4) {
            uint32_t dstb = kb + (uint32_t)(((rc + 1) & 1) * 8704 * 4);
            const float* src = Kg + (size_t)(rc + 1) * 128 * DIMC;
#pragma unroll
            for (int i = 0; i < 8; i++) {
                int id = tid + i * 256;
                int r = id >> 4, c = id & 15;
                CP_ASYNC16(dstb + (uint32_t)((r * KSTR + c * 4) * 4), src + (size_t)r * DIMC + c * 4);
            }
            CP_COMMIT();
        }
        uint32_t ksm = kb + (uint32_t)((rc & 1) * 8704 * 4) + kb_lm;
        float acc[2][4][4];
#pragma unroll
        for (int mi = 0; mi < 2; mi++)
#pragma unroll
            for (int nj = 0; nj < 4; nj++)
#pragma unroll
                for (int q = 0; q < 4; q++) acc[mi][nj][q] = 0.f;

#pragma unroll
        for (int kk = 0; kk < 64; kk += 8) {
            uint32_t a[2][4], bb[4][2];
#pragma unroll
            for (int mi = 0; mi < 2; mi++)
                ldmx4(a[mi][0], a[mi][1], a[mi][2], a[mi][3],
                      qa_lm + (uint32_t)((mi * 16 * QSTR + kk) * 4));
#pragma unroll
            for (int njg = 0; njg < 4; njg += 2)
                ldmx4(bb[njg][0], bb[njg][1], bb[njg + 1][0], bb[njg + 1][1],
                      ksm + (uint32_t)((njg * 8 * KSTR + kk) * 4));
#pragma unroll
            for (int mi = 0; mi < 2; mi++)
#pragma unroll
                for (int nj = 0; nj < 4; nj++)
                    mma_tf32(acc[mi][nj], a[mi], bb[nj]);
        }
#pragma unroll
        for (int mi = 0; mi < 2; mi++) {
            int row = wmS + mi * 16 + g;
#pragma unroll
            for (int nj = 0; nj < 4; nj++) {
                int col = rc * 128 + wnS + nj * 8 + tg * 2;
                *(float2*)&Ss[row * SSTR + col]       = make_float2(acc[mi][nj][0], acc[mi][nj][1]);
                *(float2*)&Ss[(row + 8) * SSTR + col] = make_float2(acc[mi][nj][2], acc[mi][nj][3]);
            }
        }
    }
    __syncthreads();

    for (int r = wid; r < 64; r += 8) {
        float* row = Ss + r * SSTR;
        float m = -1e30f;
        for (int c = lane; c < 512; c += 32) m = fmaxf(m, row[c]);
#pragma unroll
        for (int o = 16; o > 0; o >>= 1) m = fmaxf(m, __shfl_xor_sync(0xffffffffu, m, o));
        float s = 0.f;
        for (int c = lane; c < 512; c += 32) {
            float e = tf32_rn(__expf(row[c] - m));
            row[c] = e;
            s += e;
        }
#pragma unroll
        for (int o = 16; o > 0; o >>= 1) s += __shfl_xor_sync(0xffffffffu, s, o);
        if (lane == 0) sInv[r] = 1.f / s;
    }

    const int wmP = (wid & 3) * 16;
    const int wnP = (wid >> 2) * 32;
    const uint32_t sa_lm = sb + (uint32_t)(((wmP + a_row) * SSTR + a_kof) * 4);
    const uint32_t vb_lm = sb + (uint32_t)(KB_OFF * 4) +
                           (uint32_t)(((wnP + b_row) * VSTR + b_kof) * 4);
    float po[4][4];
#pragma unroll
    for (int nj = 0; nj < 4; nj++)
#pragma unroll
        for (int q = 0; q < 4; q++) po[nj][q] = 0.f;

    for (int rc = 0; rc < 4; rc++) {
        __syncthreads();
#pragma unroll
        for (int i = 0; i < 8; i++) {
            int id = tid + i * 256;
            int r = id & 127;
            int c = (id >> 7) * 4;
            float4 v = *(const float4*)(Vg + (size_t)(rc * 128 + r) * DIMC + c);
            KB[(c + 0) * VSTR + r] = v.x;
            KB[(c + 1) * VSTR + r] = v.y;
            KB[(c + 2) * VSTR + r] = v.z;
            KB[(c + 3) * VSTR + r] = v.w;
        }
        __syncthreads();
#pragma unroll
        for (int kk = 0; kk < 128; kk += 8) {
            uint32_t a[4], bb[4][2];
            ldmx4(a[0], a[1], a[2], a[3],
                  sa_lm + (uint32_t)((rc * 128 + kk) * 4));
#pragma unroll
            for (int njg = 0; njg < 4; njg += 2)
                ldmx4(bb[njg][0], bb[njg][1], bb[njg + 1][0], bb[njg + 1][1],
                      vb_lm + (uint32_t)((njg * 8 * VSTR + kk) * 4));
#pragma unroll
            for (int nj = 0; nj < 4; nj++)
                mma_tf32(po[nj], a, bb[nj]);
        }
    }

    // epilogue: normalize (fp32) and store fp16 for the fp16 O-projection
    float inv0 = sInv[wmP + g];
    float inv1 = sInv[wmP + g + 8];
    __half* Og = g_Oh + ((size_t)(b * LC + q0 + wmP + g)) * DIMC + h * DHC + wnP;
#pragma unroll
    for (int nj = 0; nj < 4; nj++) {
        int col = nj * 8 + tg * 2;
        *(__half2*)(Og + col) = __floats2half2_rn(po[nj][0] * inv0, po[nj][1] * inv0);
        *(__half2*)(Og + 8 * DIMC + col) = __floats2half2_rn(po[nj][2] * inv1, po[nj][3] * inv1);
    }
}

// ---------------------------------------------------------------------------
// Launch
// ---------------------------------------------------------------------------
extern "C" void kernel_launch(void* const* d_in, const int* in_sizes, int n_in,
                              void* d_out, int out_size) {
    const float* x   = (const float*)d_in[0];
    const float* ctx = (const float*)d_in[1];
    const float* Wq  = (const float*)d_in[2];
    const float* Wk  = (const float*)d_in[3];
    const float* Wv  = (const float*)d_in[4];
    const float* Wo  = (const float*)d_in[5];
    float* out = (float*)d_out;

    void *pXr, *pCr, *pWqT, *pWkvT, *pWoT, *pQ, *pK, *pV, *pOh;
    cudaGetSymbolAddress(&pXr, g_Xr);
    cudaGetSymbolAddress(&pCr, g_Cr);
    cudaGetSymbolAddress(&pWqT, g_WqT);
    cudaGetSymbolAddress(&pWkvT, g_WkvT);
    cudaGetSymbolAddress(&pWoT, g_WoT);
    cudaGetSymbolAddress(&pQ, g_Q);
    cudaGetSymbolAddress(&pK, g_K);
    cudaGetSymbolAddress(&pV, g_V);
    cudaGetSymbolAddress(&pOh, g_Oh);

    __half* WkvT0 = (__half*)pWkvT;
    __half* WkvT1 = (__half*)pWkvT + (size_t)DIMC * DIMC;

    cudaFuncSetAttribute(mma_gemm_kernel, cudaFuncAttributeMaxDynamicSharedMemorySize, GSM_TOTAL);
    cudaFuncSetAttribute(attn_mma_kernel, cudaFuncAttributeMaxDynamicSharedMemorySize, ATTN_SMEM);

    round_copy_h_kernel<<<(BC * LC * DIMC / 4 + 255) / 256, 256>>>(x,   (__half*)pXr, BC * LC * DIMC / 4);  // 0
    round_copy_h_kernel<<<(BC * RC * DIMC / 4 + 255) / 256, 256>>>(ctx, (__half*)pCr, BC * RC * DIMC / 4);  // 1
    dim3 tg3(DIMC / 32, DIMC / 32, 4);
    transpose_all_kernel<<<tg3, 256>>>(Wq, Wk, Wv, Wo,                                                       // 2
                                       (__half*)pWqT, WkvT0, WkvT1, (__half*)pWoT);

    // 3: fused K+V projection (N = 2048, split at 1024)
    mma_gemm_kernel<<<dim3(2 * DIMC / 128, (BC * RC) / 128), 256, GSM_TOTAL>>>(
        (const __half*)pCr, (const __half*)pWkvT, (float*)pK, (float*)pV, DIMC, 1);
    // 4: Q projection
    mma_gemm_kernel<<<dim3(DIMC / 128, (BC * LC) / 128), 256, GSM_TOTAL>>>(
        (const __half*)pXr, (const __half*)pWqT, (float*)pQ, (float*)pQ, 1 << 30, 1);
    // 5: attention  <- ncu -s 5 profiles this
    attn_mma_kernel<<<dim3(LC / 64, BC * HC), 256, ATTN_SMEM>>>();
    // 6: output projection (fp32 out)
    mma_gemm_kernel<<<dim3(DIMC / 128, (BC * LC) / 128), 256, GSM_TOTAL>>>(
        (const __half*)pOh, (const __half*)pWoT, out, out, 1 << 30, 0);
}

// round 15
// speedup vs baseline: 2.6623x; 1.6747x over previous
#include <cuda_runtime.h>
#include <cuda_fp16.h>
#include <cstdint>
#include <math.h>

// Problem constants
#define DIMC 1024
#define HC   16
#define DHC  64
#define BC   4
#define LC   4096
#define RC   512
#define SCALEF 0.125f   // 64^-0.5

// ---------------------------------------------------------------------------
// Device-global scratch (all activations fp16)
// ---------------------------------------------------------------------------
__device__ __half g_Qh [(size_t)BC * LC * DIMC];   // Q (pre-scaled), fp16
__device__ __half g_Kh [(size_t)BC * RC * DIMC];
__device__ __half g_Vh [(size_t)BC * RC * DIMC];
__device__ __half g_Oh [(size_t)BC * LC * DIMC];   // attention out
__device__ __half g_Xr [(size_t)BC * LC * DIMC];
__device__ __half g_Cr [(size_t)BC * RC * DIMC];
__device__ __half g_WqT [(size_t)DIMC * DIMC];
__device__ __half g_WkvT[(size_t)2 * DIMC * DIMC];
__device__ __half g_WoT [(size_t)DIMC * DIMC];

// ---------------------------------------------------------------------------
// Helpers
// ---------------------------------------------------------------------------
__device__ __forceinline__ uint32_t smem_u32(const void* p) {
    uint32_t a;
    asm("{ .reg .u64 t; cvta.to.shared.u64 t, %1; cvt.u32.u64 %0, t; }" : "=r"(a) : "l"(p));
    return a;
}

#define CP_ASYNC16(dst, src) \
    asm volatile("cp.async.cg.shared.global [%0], [%1], 16;" :: "r"(dst), "l"(src) : "memory")
#define CP_COMMIT() asm volatile("cp.async.commit_group;" ::: "memory")
#define CP_WAIT(n)  asm volatile("cp.async.wait_group %0;" :: "n"(n) : "memory")

__device__ __forceinline__ void mma_f16(float* c, const uint32_t* a, const uint32_t* b) {
    asm volatile(
        "mma.sync.aligned.m16n8k16.row.col.f32.f16.f16.f32 "
        "{%0,%1,%2,%3}, {%4,%5,%6,%7}, {%8,%9}, {%0,%1,%2,%3};"
        : "+f"(c[0]), "+f"(c[1]), "+f"(c[2]), "+f"(c[3])
        : "r"(a[0]), "r"(a[1]), "r"(a[2]), "r"(a[3]), "r"(b[0]), "r"(b[1]));
}

__device__ __forceinline__ void ldmx4(uint32_t& r0, uint32_t& r1, uint32_t& r2, uint32_t& r3,
                                      uint32_t addr) {
    asm volatile("ldmatrix.sync.aligned.m8n8.x4.shared.b16 {%0,%1,%2,%3}, [%4];"
                 : "=r"(r0), "=r"(r1), "=r"(r2), "=r"(r3) : "r"(addr));
}
__device__ __forceinline__ void ldmx4t(uint32_t& r0, uint32_t& r1, uint32_t& r2, uint32_t& r3,
                                       uint32_t addr) {
    asm volatile("ldmatrix.sync.aligned.m8n8.x4.trans.shared.b16 {%0,%1,%2,%3}, [%4];"
                 : "=r"(r0), "=r"(r1), "=r"(r2), "=r"(r3) : "r"(addr));
}

// ---------------------------------------------------------------------------
// Preprocessing kernels (fp32 -> fp16)
// ---------------------------------------------------------------------------
__global__ __launch_bounds__(256) void round_copy_h_kernel(const float* __restrict__ src,
                                                           __half* __restrict__ dst, int n4) {
    int i = blockIdx.x * 256 + threadIdx.x;
    if (i < n4) {
        float4 v = ((const float4*)src)[i];
        ((__half2*)dst)[2 * i]     = __floats2half2_rn(v.x, v.y);
        ((__half2*)dst)[2 * i + 1] = __floats2half2_rn(v.z, v.w);
    }
}

__global__ __launch_bounds__(256) void transpose_all_kernel(const float* __restrict__ W0,
                                                            const float* __restrict__ W1,
                                                            const float* __restrict__ W2,
                                                            const float* __restrict__ W3,
                                                            __half* __restrict__ T0,
                                                            __half* __restrict__ T1,
                                                            __half* __restrict__ T2,
                                                            __half* __restrict__ T3) {
    __shared__ float t[32][33];
    const float* W;
    __half* Wt;
    float scale = 1.0f;
    switch (blockIdx.z) {
        case 0: W = W0; Wt = T0; scale = SCALEF; break;
        case 1: W = W1; Wt = T1; break;
        case 2: W = W2; Wt = T2; break;
        default: W = W3; Wt = T3; break;
    }
    int tx = threadIdx.x & 31;
    int ty = threadIdx.x >> 5;
    int x = blockIdx.x * 32 + tx;
#pragma unroll
    for (int i = ty; i < 32; i += 8) {
        int y = blockIdx.y * 32 + i;
        t[i][tx] = W[(size_t)y * DIMC + x] * scale;
    }
    __syncthreads();
    int xo = blockIdx.y * 32 + tx;
#pragma unroll
    for (int i = ty; i < 32; i += 8) {
        int yo = blockIdx.x * 32 + i;
        Wt[(size_t)yo * DIMC + xo] = __float2half_rn(t[tx][i]);
    }
}

// ---------------------------------------------------------------------------
// fp16 mma.sync GEMM: 128x128 CTA tile, BK=64 halfs, swizzled 128B rows,
// 3-stage cp.async, ldmatrix, 2 CTAs/SM.
// half_out=1 -> store fp16 (Q/K/V); 0 -> store fp32 (final output).
// ---------------------------------------------------------------------------
#define BKH 64
#define TILE_BYTES (128 * 128)
#define STG_BYTES  (2 * TILE_BYTES)
#define GSM_TOTAL  (3 * STG_BYTES)           // 98304 B

__device__ __forceinline__ void load_stage(uint32_t sbase, const __half* __restrict__ Ab,
                                           const __half* __restrict__ Bb, int kt, int tid) {
    uint32_t sA = sbase;
    uint32_t sB = sbase + TILE_BYTES;
    const __half* As_ = Ab + kt * BKH;
    const __half* Bs_ = Bb + kt * BKH;
#pragma unroll
    for (int i = 0; i < 4; i++) {
        int id = tid + i * 256;
        int r = id >> 3;
        int gr = id & 7;
        uint32_t off = (uint32_t)(r * 128 + ((gr ^ (r & 7)) << 4));
        CP_ASYNC16(sA + off, As_ + (size_t)r * DIMC + gr * 8);
        CP_ASYNC16(sB + off, Bs_ + (size_t)r * DIMC + gr * 8);
    }
}

__global__ __launch_bounds__(256, 2) void mma_gemm_kernel(const __half* __restrict__ A,
                                                          const __half* __restrict__ Bt,
                                                          void* __restrict__ C,
                                                          void* __restrict__ C2,
                                                          int nsplit,
                                                          int half_out) {
    extern __shared__ float sm[];
    const int tid = threadIdx.x;
    const int lane = tid & 31;
    const int g = lane >> 2;
    const int tg = lane & 3;
    const int wid = tid >> 5;
    const int wm = (wid & 3) * 32;
    const int wn = (wid >> 2) * 64;

    const int a_row = (lane & 7) + ((lane >> 3) & 1) * 8;
    const int a_g   = lane >> 4;
    const int b_row = (lane & 7) + (lane >> 4) * 8;
    const int b_g   = (lane >> 3) & 1;

    const __half* Ab = A  + (size_t)blockIdx.y * 128 * DIMC;
    const __half* Bb = Bt + (size_t)blockIdx.x * 128 * DIMC;
    uint32_t sb = smem_u32(sm);

    uint32_t aBase[2], bBase[4];
    int aX[2], bX[4];
#pragma unroll
    for (int mi = 0; mi < 2; mi++) {
        int R = wm + a_row + mi * 16;
        aBase[mi] = (uint32_t)(R * 128);
        aX[mi] = R & 7;
    }
#pragma unroll
    for (int j = 0; j < 4; j++) {
        int R = wn + b_row + j * 16;
        bBase[j] = (uint32_t)(TILE_BYTES + R * 128);
        bX[j] = R & 7;
    }

    float acc[2][8][4];
#pragma unroll
    for (int mi = 0; mi < 2; mi++)
#pragma unroll
        for (int nj = 0; nj < 8; nj++)
#pragma unroll
            for (int q = 0; q < 4; q++) acc[mi][nj][q] = 0.f;

    load_stage(sb + 0 * STG_BYTES, Ab, Bb, 0, tid); CP_COMMIT();
    load_stage(sb + 1 * STG_BYTES, Ab, Bb, 1, tid); CP_COMMIT();

    const int NKT = DIMC / BKH;   // 16
    for (int kt = 0; kt < NKT; kt++) {
        if (kt < NKT - 1) { CP_WAIT(1); } else { CP_WAIT(0); }
        __syncthreads();

        uint32_t stg = sb + (uint32_t)((kt % 3) * STG_BYTES);

#pragma unroll
        for (int kk = 0; kk < BKH; kk += 16) {
            int Ga = (kk >> 3) + a_g;
            int Gb = (kk >> 3) + b_g;
            uint32_t a[2][4], b[8][2];
#pragma unroll
            for (int mi = 0; mi < 2; mi++)
                ldmx4(a[mi][0], a[mi][1], a[mi][2], a[mi][3],
                      stg + aBase[mi] + (uint32_t)((Ga ^ aX[mi]) << 4));
#pragma unroll
            for (int j = 0; j < 4; j++)
                ldmx4(b[2 * j][0], b[2 * j][1], b[2 * j + 1][0], b[2 * j + 1][1],
                      stg + bBase[j] + (uint32_t)((Gb ^ bX[j]) << 4));
#pragma unroll
            for (int mi = 0; mi < 2; mi++)
#pragma unroll
                for (int nj = 0; nj < 8; nj++)
                    mma_f16(acc[mi][nj], a[mi], b[nj]);
        }

        if (kt + 2 < NKT) {
            load_stage(sb + (uint32_t)(((kt + 2) % 3) * STG_BYTES), Ab, Bb, kt + 2, tid);
            CP_COMMIT();
        }
    }

    int colb = blockIdx.x * 128;
    void* Cout = C;
    if (colb >= nsplit) { Cout = C2; colb -= nsplit; }
    size_t rowb = (size_t)blockIdx.y * 128 + wm + g;

    if (half_out) {
#pragma unroll
        for (int mi = 0; mi < 2; mi++) {
            __half* C0 = (__half*)Cout + (rowb + mi * 16) * DIMC + colb + wn;
            __half* C1 = C0 + 8 * DIMC;
#pragma unroll
            for (int nj = 0; nj < 8; nj++) {
                *(__half2*)(C0 + nj * 8 + tg * 2) = __floats2half2_rn(acc[mi][nj][0], acc[mi][nj][1]);
                *(__half2*)(C1 + nj * 8 + tg * 2) = __floats2half2_rn(acc[mi][nj][2], acc[mi][nj][3]);
            }
        }
    } else {
#pragma unroll
        for (int mi = 0; mi < 2; mi++) {
            float* C0 = (float*)Cout + (rowb + mi * 16) * DIMC + colb + wn;
            float* C1 = C0 + 8 * DIMC;
#pragma unroll
            for (int nj = 0; nj < 8; nj++) {
                *(float2*)(C0 + nj * 8 + tg * 2) = make_float2(acc[mi][nj][0], acc[mi][nj][1]);
                *(float2*)(C1 + nj * 8 + tg * 2) = make_float2(acc[mi][nj][2], acc[mi][nj][3]);
            }
        }
    }
}

// ---------------------------------------------------------------------------
// fp16 tensor-core attention: one CTA = (b,h) x 64 q rows.
//   S(64x512) fp32 in smem = Q(fp16) @ K^T(fp16)
//   softmax fp32; P stored fp16 in-place in S row storage
//   O = P @ V via ldmatrix.trans on untransposed fp16 V chunks
// smem (bytes): S 132096 | Q 8192 | KV 2x16384 | inv 256 = 173312
// ---------------------------------------------------------------------------
#define SSTR 516
#define SROWB 2064
#define Q_OFFB   132096
#define KB_OFFB  140288
#define INV_OFFB 173056
#define ATTN_SMEM 173312

__global__ __launch_bounds__(256) void attn_mma_kernel() {
    extern __shared__ char smc[];
    float* Ss = (float*)smc;
    float* sInv = (float*)(smc + INV_OFFB);
    uint32_t sb = smem_u32(smc);
    const uint32_t qb = sb + Q_OFFB;
    const uint32_t kb = sb + KB_OFFB;

    const int tid = threadIdx.x;
    const int lane = tid & 31;
    const int g = lane >> 2;
    const int tg = lane & 3;
    const int wid = tid >> 5;
    const int bh = blockIdx.y;
    const int b = bh >> 4;
    const int h = bh & 15;
    const int q0 = blockIdx.x * 64;

    const int a_row = (lane & 7) + ((lane >> 3) & 1) * 8;
    const int a_g   = lane >> 4;
    const int b_row = (lane & 7) + (lane >> 4) * 8;
    const int b_g   = (lane >> 3) & 1;

    const __half* Qg = g_Qh + ((size_t)(b * LC + q0)) * DIMC + h * DHC;
    const __half* Kg = g_Kh + ((size_t)(b * RC)) * DIMC + h * DHC;
    const __half* Vg = g_Vh + ((size_t)(b * RC)) * DIMC + h * DHC;

    // prologue: Q tile (64x64h = 512 granules) + K chunk 0 (128x64h = 1024 granules)
#pragma unroll
    for (int i = 0; i < 2; i++) {
        int id = tid + i * 256;
        int r = id >> 3, gr = id & 7;
        CP_ASYNC16(qb + (uint32_t)(r * 128 + ((gr ^ (r & 7)) << 4)), Qg + (size_t)r * DIMC + gr * 8);
    }
#pragma unroll
    for (int i = 0; i < 4; i++) {
        int id = tid + i * 256;
        int r = id >> 3, gr = id & 7;
        CP_ASYNC16(kb + (uint32_t)(r * 128 + ((gr ^ (r & 7)) << 4)), Kg + (size_t)r * DIMC + gr * 8);
    }
    CP_COMMIT();

    // ---- S phase: 8 warps as 2m x 4n (32x32 warp tiles), fp16 k=16 ----
    const int wmS = (wid & 1) * 32;
    const int wnS = (wid >> 1) * 32;
    uint32_t aQ[2]; int aXq[2];
#pragma unroll
    for (int mi = 0; mi < 2; mi++) {
        int R = wmS + a_row + mi * 16;
        aQ[mi] = qb + (uint32_t)(R * 128);
        aXq[mi] = R & 7;
    }
    uint32_t bK[2]; int bXk[2];
#pragma unroll
    for (int j = 0; j < 2; j++) {
        int R = wnS + b_row + j * 16;
        bK[j] = (uint32_t)(R * 128);
        bXk[j] = R & 7;
    }

    for (int rc = 0; rc < 4; rc++) {
        CP_WAIT(0);
        __syncthreads();
        {   // prefetch next K chunk, or V chunk 0 after the last K
            const __half* src = (rc + 1 < 4) ? (Kg + (size_t)(rc + 1) * 128 * DIMC) : Vg;
            uint32_t dstb = kb + (uint32_t)(((rc + 1) & 1) * TILE_BYTES);
#pragma unroll
            for (int i = 0; i < 4; i++) {
                int id = tid + i * 256;
                int r = id >> 3, gr = id & 7;
                CP_ASYNC16(dstb + (uint32_t)(r * 128 + ((gr ^ (r & 7)) << 4)),
                           src + (size_t)r * DIMC + gr * 8);
            }
            CP_COMMIT();
        }
        uint32_t kbuf = kb + (uint32_t)((rc & 1) * TILE_BYTES);
        float acc[2][4][4];
#pragma unroll
        for (int mi = 0; mi < 2; mi++)
#pragma unroll
            for (int nj = 0; nj < 4; nj++)
#pragma unroll
                for (int q = 0; q < 4; q++) acc[mi][nj][q] = 0.f;

#pragma unroll
        for (int kk = 0; kk < 64; kk += 16) {
            int Ga = (kk >> 3) + a_g;
            int Gb = (kk >> 3) + b_g;
            uint32_t a[2][4], bb[4][2];
#pragma unroll
            for (int mi = 0; mi < 2; mi++)
                ldmx4(a[mi][0], a[mi][1], a[mi][2], a[mi][3],
                      aQ[mi] + (uint32_t)((Ga ^ aXq[mi]) << 4));
#pragma unroll
            for (int j = 0; j < 2; j++)
                ldmx4(bb[2 * j][0], bb[2 * j][1], bb[2 * j + 1][0], bb[2 * j + 1][1],
                      kbuf + bK[j] + (uint32_t)((Gb ^ bXk[j]) << 4));
#pragma unroll
            for (int mi = 0; mi < 2; mi++)
#pragma unroll
                for (int nj = 0; nj < 4; nj++)
                    mma_f16(acc[mi][nj], a[mi], bb[nj]);
        }
#pragma unroll
        for (int mi = 0; mi < 2; mi++) {
            int row = wmS + mi * 16 + g;
#pragma unroll
            for (int nj = 0; nj < 4; nj++) {
                int col = rc * 128 + wnS + nj * 8 + tg * 2;
                *(float2*)&Ss[row * SSTR + col]       = make_float2(acc[mi][nj][0], acc[mi][nj][1]);
                *(float2*)&Ss[(row + 8) * SSTR + col] = make_float2(acc[mi][nj][2], acc[mi][nj][3]);
            }
        }
    }
    __syncthreads();

    // ---- softmax (fp32 scores); P written fp16 in-place in each S row ----
    for (int r = wid; r < 64; r += 8) {
        float* row = Ss + r * SSTR;
        __half* prow = (__half*)row;
        float m = -1e30f;
        for (int c = lane; c < 512; c += 32) m = fmaxf(m, row[c]);
#pragma unroll
        for (int o = 16; o > 0; o >>= 1) m = fmaxf(m, __shfl_xor_sync(0xffffffffu, m, o));
        float e16[16];
        float s = 0.f;
#pragma unroll
        for (int j = 0; j < 16; j++) {
            float e = __expf(row[lane + 32 * j] - m);
            e16[j] = e;
            s += e;
        }
#pragma unroll
        for (int o = 16; o > 0; o >>= 1) s += __shfl_xor_sync(0xffffffffu, s, o);
#pragma unroll
        for (int j = 0; j < 16; j++) prow[lane + 32 * j] = __float2half_rn(e16[j]);
        if (lane == 0) sInv[r] = 1.f / s;
    }

    // ---- PV phase: 8 warps as 4m x 2n (16x32 warp tiles), fp16 ----
    const int wmP = (wid & 3) * 16;
    const int wnP = (wid >> 2) * 32;
    const uint32_t pA = sb + (uint32_t)((wmP + a_row) * SROWB);
    float po[4][4];
#pragma unroll
    for (int nj = 0; nj < 4; nj++)
#pragma unroll
        for (int q = 0; q < 4; q++) po[nj][q] = 0.f;

    for (int rc = 0; rc < 4; rc++) {
        CP_WAIT(0);
        __syncthreads();
        if (rc + 1 < 4) {   // prefetch next V chunk
            const __half* src = Vg + (size_t)(rc + 1) * 128 * DIMC;
            uint32_t dstb = kb + (uint32_t)(((rc + 1) & 1) * TILE_BYTES);
#pragma unroll
            for (int i = 0; i < 4; i++) {
                int id = tid + i * 256;
                int r = id >> 3, gr = id & 7;
                CP_ASYNC16(dstb + (uint32_t)(r * 128 + ((gr ^ (r & 7)) << 4)),
                           src + (size_t)r * DIMC + gr * 8);
            }
            CP_COMMIT();
        }
        uint32_t vbuf = kb + (uint32_t)((rc & 1) * TILE_BYTES);
#pragma unroll
        for (int kk = 0; kk < 128; kk += 16) {
            uint32_t a[4], bb[4][2];
            ldmx4(a[0], a[1], a[2], a[3],
                  pA + (uint32_t)((rc * 16 + (kk >> 3) + a_g) << 4));
#pragma unroll
            for (int j = 0; j < 2; j++) {
                int R = kk + a_row;
                int gn = (wnP >> 3) + 2 * j + a_g;
                ldmx4t(bb[2 * j][0], bb[2 * j][1], bb[2 * j + 1][0], bb[2 * j + 1][1],
                       vbuf + (uint32_t)(R * 128 + ((gn ^ (R & 7)) << 4)));
            }
#pragma unroll
            for (int nj = 0; nj < 4; nj++)
                mma_f16(po[nj], a, bb[nj]);
        }
    }

    // ---- epilogue: normalize (fp32), store fp16 ----
    float inv0 = sInv[wmP + g];
    float inv1 = sInv[wmP + g + 8];
    __half* Og = g_Oh + ((size_t)(b * LC + q0 + wmP + g)) * DIMC + h * DHC + wnP;
#pragma unroll
    for (int nj = 0; nj < 4; nj++) {
        int col = nj * 8 + tg * 2;
        *(__half2*)(Og + col) = __floats2half2_rn(po[nj][0] * inv0, po[nj][1] * inv0);
        *(__half2*)(Og + 8 * DIMC + col) = __floats2half2_rn(po[nj][2] * inv1, po[nj][3] * inv1);
    }
}

// ---------------------------------------------------------------------------
// Launch
// ---------------------------------------------------------------------------
extern "C" void kernel_launch(void* const* d_in, const int* in_sizes, int n_in,
                              void* d_out, int out_size) {
    const float* x   = (const float*)d_in[0];
    const float* ctx = (const float*)d_in[1];
    const float* Wq  = (const float*)d_in[2];
    const float* Wk  = (const float*)d_in[3];
    const float* Wv  = (const float*)d_in[4];
    const float* Wo  = (const float*)d_in[5];
    float* out = (float*)d_out;

    void *pXr, *pCr, *pWqT, *pWkvT, *pWoT, *pQ, *pK, *pV, *pOh;
    cudaGetSymbolAddress(&pXr, g_Xr);
    cudaGetSymbolAddress(&pCr, g_Cr);
    cudaGetSymbolAddress(&pWqT, g_WqT);
    cudaGetSymbolAddress(&pWkvT, g_WkvT);
    cudaGetSymbolAddress(&pWoT, g_WoT);
    cudaGetSymbolAddress(&pQ, g_Qh);
    cudaGetSymbolAddress(&pK, g_Kh);
    cudaGetSymbolAddress(&pV, g_Vh);
    cudaGetSymbolAddress(&pOh, g_Oh);

    __half* WkvT0 = (__half*)pWkvT;
    __half* WkvT1 = (__half*)pWkvT + (size_t)DIMC * DIMC;

    cudaFuncSetAttribute(mma_gemm_kernel, cudaFuncAttributeMaxDynamicSharedMemorySize, GSM_TOTAL);
    cudaFuncSetAttribute(attn_mma_kernel, cudaFuncAttributeMaxDynamicSharedMemorySize, ATTN_SMEM);

    round_copy_h_kernel<<<(BC * LC * DIMC / 4 + 255) / 256, 256>>>(x,   (__half*)pXr, BC * LC * DIMC / 4);  // 0
    round_copy_h_kernel<<<(BC * RC * DIMC / 4 + 255) / 256, 256>>>(ctx, (__half*)pCr, BC * RC * DIMC / 4);  // 1
    dim3 tg3(DIMC / 32, DIMC / 32, 4);
    transpose_all_kernel<<<tg3, 256>>>(Wq, Wk, Wv, Wo,                                                       // 2
                                       (__half*)pWqT, WkvT0, WkvT1, (__half*)pWoT);

    // 3: fused K+V projection (fp16 out)
    mma_gemm_kernel<<<dim3(2 * DIMC / 128, (BC * RC) / 128), 256, GSM_TOTAL>>>(
        (const __half*)pCr, (const __half*)pWkvT, pK, pV, DIMC, 1);
    // 4: Q projection (fp16 out)
    mma_gemm_kernel<<<dim3(DIMC / 128, (BC * LC) / 128), 256, GSM_TOTAL>>>(
        (const __half*)pXr, (const __half*)pWqT, pQ, pQ, 1 << 30, 1);
    // 5: attention  <- ncu -s 5 profiles this
    attn_mma_kernel<<<dim3(LC / 64, BC * HC), 256, ATTN_SMEM>>>();
    // 6: output projection (fp32 out)
    mma_gemm_kernel<<<dim3(DIMC / 128, (BC * LC) / 128), 256, GSM_TOTAL>>>(
        (const __half*)pOh, (const __half*)pWoT, (void*)out, (void*)out, 1 << 30, 0);
}

// round 16
// speedup vs baseline: 3.4749x; 1.3052x over previous
#include <cuda_runtime.h>
#include <cuda_fp16.h>
#include <cstdint>
#include <math.h>

// Problem constants
#define DIMC 1024
#define HC   16
#define DHC  64
#define BC   4
#define LC   4096
#define RC   512
#define SCALEF 0.125f   // 64^-0.5

// ---------------------------------------------------------------------------
// Device-global scratch (all activations fp16)
// ---------------------------------------------------------------------------
__device__ __half g_Qh [(size_t)BC * LC * DIMC];
__device__ __half g_Kh [(size_t)BC * RC * DIMC];
__device__ __half g_Vh [(size_t)BC * RC * DIMC];
__device__ __half g_Oh [(size_t)BC * LC * DIMC];
__device__ __half g_Xr [(size_t)BC * LC * DIMC];
__device__ __half g_Cr [(size_t)BC * RC * DIMC];
__device__ __half g_WqT [(size_t)DIMC * DIMC];
__device__ __half g_WkvT[(size_t)2 * DIMC * DIMC];
__device__ __half g_WoT [(size_t)DIMC * DIMC];

// ---------------------------------------------------------------------------
// Helpers
// ---------------------------------------------------------------------------
__device__ __forceinline__ uint32_t smem_u32(const void* p) {
    uint32_t a;
    asm("{ .reg .u64 t; cvta.to.shared.u64 t, %1; cvt.u32.u64 %0, t; }" : "=r"(a) : "l"(p));
    return a;
}

#define CP_ASYNC16(dst, src) \
    asm volatile("cp.async.cg.shared.global [%0], [%1], 16;" :: "r"(dst), "l"(src) : "memory")
#define CP_COMMIT() asm volatile("cp.async.commit_group;" ::: "memory")
#define CP_WAIT(n)  asm volatile("cp.async.wait_group %0;" :: "n"(n) : "memory")

__device__ __forceinline__ void mma_f16(float* c, const uint32_t* a, const uint32_t* b) {
    asm volatile(
        "mma.sync.aligned.m16n8k16.row.col.f32.f16.f16.f32 "
        "{%0,%1,%2,%3}, {%4,%5,%6,%7}, {%8,%9}, {%0,%1,%2,%3};"
        : "+f"(c[0]), "+f"(c[1]), "+f"(c[2]), "+f"(c[3])
        : "r"(a[0]), "r"(a[1]), "r"(a[2]), "r"(a[3]), "r"(b[0]), "r"(b[1]));
}

__device__ __forceinline__ void ldmx4(uint32_t& r0, uint32_t& r1, uint32_t& r2, uint32_t& r3,
                                      uint32_t addr) {
    asm volatile("ldmatrix.sync.aligned.m8n8.x4.shared.b16 {%0,%1,%2,%3}, [%4];"
                 : "=r"(r0), "=r"(r1), "=r"(r2), "=r"(r3) : "r"(addr));
}
__device__ __forceinline__ void ldmx4t(uint32_t& r0, uint32_t& r1, uint32_t& r2, uint32_t& r3,
                                       uint32_t addr) {
    asm volatile("ldmatrix.sync.aligned.m8n8.x4.trans.shared.b16 {%0,%1,%2,%3}, [%4];"
                 : "=r"(r0), "=r"(r1), "=r"(r2), "=r"(r3) : "r"(addr));
}
__device__ __forceinline__ uint32_t h2u(float a, float b) {
    __half2 h = __floats2half2_rn(a, b);
    return *(uint32_t*)&h;
}

// ---------------------------------------------------------------------------
// Preprocessing kernels (fp32 -> fp16)
// ---------------------------------------------------------------------------
__global__ __launch_bounds__(256) void round_copy_h_kernel(const float* __restrict__ src,
                                                           __half* __restrict__ dst, int n4) {
    int i = blockIdx.x * 256 + threadIdx.x;
    if (i < n4) {
        float4 v = ((const float4*)src)[i];
        ((__half2*)dst)[2 * i]     = __floats2half2_rn(v.x, v.y);
        ((__half2*)dst)[2 * i + 1] = __floats2half2_rn(v.z, v.w);
    }
}

__global__ __launch_bounds__(256) void transpose_all_kernel(const float* __restrict__ W0,
                                                            const float* __restrict__ W1,
                                                            const float* __restrict__ W2,
                                                            const float* __restrict__ W3,
                                                            __half* __restrict__ T0,
                                                            __half* __restrict__ T1,
                                                            __half* __restrict__ T2,
                                                            __half* __restrict__ T3) {
    __shared__ float t[32][33];
    const float* W;
    __half* Wt;
    float scale = 1.0f;
    switch (blockIdx.z) {
        case 0: W = W0; Wt = T0; scale = SCALEF; break;
        case 1: W = W1; Wt = T1; break;
        case 2: W = W2; Wt = T2; break;
        default: W = W3; Wt = T3; break;
    }
    int tx = threadIdx.x & 31;
    int ty = threadIdx.x >> 5;
    int x = blockIdx.x * 32 + tx;
#pragma unroll
    for (int i = ty; i < 32; i += 8) {
        int y = blockIdx.y * 32 + i;
        t[i][tx] = W[(size_t)y * DIMC + x] * scale;
    }
    __syncthreads();
    int xo = blockIdx.y * 32 + tx;
#pragma unroll
    for (int i = ty; i < 32; i += 8) {
        int yo = blockIdx.x * 32 + i;
        Wt[(size_t)yo * DIMC + xo] = __float2half_rn(t[tx][i]);
    }
}

// ---------------------------------------------------------------------------
// fp16 mma.sync GEMM (unchanged from R15)
// ---------------------------------------------------------------------------
#define BKH 64
#define TILE_BYTES (128 * 128)
#define STG_BYTES  (2 * TILE_BYTES)
#define GSM_TOTAL  (3 * STG_BYTES)           // 98304 B

__device__ __forceinline__ void load_stage(uint32_t sbase, const __half* __restrict__ Ab,
                                           const __half* __restrict__ Bb, int kt, int tid) {
    uint32_t sA = sbase;
    uint32_t sB = sbase + TILE_BYTES;
    const __half* As_ = Ab + kt * BKH;
    const __half* Bs_ = Bb + kt * BKH;
#pragma unroll
    for (int i = 0; i < 4; i++) {
        int id = tid + i * 256;
        int r = id >> 3;
        int gr = id & 7;
        uint32_t off = (uint32_t)(r * 128 + ((gr ^ (r & 7)) << 4));
        CP_ASYNC16(sA + off, As_ + (size_t)r * DIMC + gr * 8);
        CP_ASYNC16(sB + off, Bs_ + (size_t)r * DIMC + gr * 8);
    }
}

__global__ __launch_bounds__(256, 2) void mma_gemm_kernel(const __half* __restrict__ A,
                                                          const __half* __restrict__ Bt,
                                                          void* __restrict__ C,
                                                          void* __restrict__ C2,
                                                          int nsplit,
                                                          int half_out) {
    extern __shared__ float sm[];
    const int tid = threadIdx.x;
    const int lane = tid & 31;
    const int g = lane >> 2;
    const int tg = lane & 3;
    const int wid = tid >> 5;
    const int wm = (wid & 3) * 32;
    const int wn = (wid >> 2) * 64;

    const int a_row = (lane & 7) + ((lane >> 3) & 1) * 8;
    const int a_g   = lane >> 4;
    const int b_row = (lane & 7) + (lane >> 4) * 8;
    const int b_g   = (lane >> 3) & 1;

    const __half* Ab = A  + (size_t)blockIdx.y * 128 * DIMC;
    const __half* Bb = Bt + (size_t)blockIdx.x * 128 * DIMC;
    uint32_t sb = smem_u32(sm);

    uint32_t aBase[2], bBase[4];
    int aX[2], bX[4];
#pragma unroll
    for (int mi = 0; mi < 2; mi++) {
        int R = wm + a_row + mi * 16;
        aBase[mi] = (uint32_t)(R * 128);
        aX[mi] = R & 7;
    }
#pragma unroll
    for (int j = 0; j < 4; j++) {
        int R = wn + b_row + j * 16;
        bBase[j] = (uint32_t)(TILE_BYTES + R * 128);
        bX[j] = R & 7;
    }

    float acc[2][8][4];
#pragma unroll
    for (int mi = 0; mi < 2; mi++)
#pragma unroll
        for (int nj = 0; nj < 8; nj++)
#pragma unroll
            for (int q = 0; q < 4; q++) acc[mi][nj][q] = 0.f;

    load_stage(sb + 0 * STG_BYTES, Ab, Bb, 0, tid); CP_COMMIT();
    load_stage(sb + 1 * STG_BYTES, Ab, Bb, 1, tid); CP_COMMIT();

    const int NKT = DIMC / BKH;   // 16
    for (int kt = 0; kt < NKT; kt++) {
        if (kt < NKT - 1) { CP_WAIT(1); } else { CP_WAIT(0); }
        __syncthreads();

        uint32_t stg = sb + (uint32_t)((kt % 3) * STG_BYTES);

#pragma unroll
        for (int kk = 0; kk < BKH; kk += 16) {
            int Ga = (kk >> 3) + a_g;
            int Gb = (kk >> 3) + b_g;
            uint32_t a[2][4], b[8][2];
#pragma unroll
            for (int mi = 0; mi < 2; mi++)
                ldmx4(a[mi][0], a[mi][1], a[mi][2], a[mi][3],
                      stg + aBase[mi] + (uint32_t)((Ga ^ aX[mi]) << 4));
#pragma unroll
            for (int j = 0; j < 4; j++)
                ldmx4(b[2 * j][0], b[2 * j][1], b[2 * j + 1][0], b[2 * j + 1][1],
                      stg + bBase[j] + (uint32_t)((Gb ^ bX[j]) << 4));
#pragma unroll
            for (int mi = 0; mi < 2; mi++)
#pragma unroll
                for (int nj = 0; nj < 8; nj++)
                    mma_f16(acc[mi][nj], a[mi], b[nj]);
        }

        if (kt + 2 < NKT) {
            load_stage(sb + (uint32_t)(((kt + 2) % 3) * STG_BYTES), Ab, Bb, kt + 2, tid);
            CP_COMMIT();
        }
    }

    int colb = blockIdx.x * 128;
    void* Cout = C;
    if (colb >= nsplit) { Cout = C2; colb -= nsplit; }
    size_t rowb = (size_t)blockIdx.y * 128 + wm + g;

    if (half_out) {
#pragma unroll
        for (int mi = 0; mi < 2; mi++) {
            __half* C0 = (__half*)Cout + (rowb + mi * 16) * DIMC + colb + wn;
            __half* C1 = C0 + 8 * DIMC;
#pragma unroll
            for (int nj = 0; nj < 8; nj++) {
                *(__half2*)(C0 + nj * 8 + tg * 2) = __floats2half2_rn(acc[mi][nj][0], acc[mi][nj][1]);
                *(__half2*)(C1 + nj * 8 + tg * 2) = __floats2half2_rn(acc[mi][nj][2], acc[mi][nj][3]);
            }
        }
    } else {
#pragma unroll
        for (int mi = 0; mi < 2; mi++) {
            float* C0 = (float*)Cout + (rowb + mi * 16) * DIMC + colb + wn;
            float* C1 = C0 + 8 * DIMC;
#pragma unroll
            for (int nj = 0; nj < 8; nj++) {
                *(float2*)(C0 + nj * 8 + tg * 2) = make_float2(acc[mi][nj][0], acc[mi][nj][1]);
                *(float2*)(C1 + nj * 8 + tg * 2) = make_float2(acc[mi][nj][2], acc[mi][nj][3]);
            }
        }
    }
}

// ---------------------------------------------------------------------------
// Flash attention (fp16 mma, register S/P, online softmax)
// CTA = 128 q rows x (b,h); 8 warps, each owns 16 q rows.
// R processed in 4 chunks of 128; K/V double-buffered in smem.
// smem: Q 16KB @0 | K0 @16K | V0 @32K | K1 @48K | V1 @64K  = 80 KB
// ---------------------------------------------------------------------------
#define AFL_SMEM 81920

__device__ __forceinline__ void attn_load_chunk(uint32_t dst, const __half* __restrict__ src,
                                                int tid) {
#pragma unroll
    for (int i = 0; i < 4; i++) {
        int id = tid + i * 256;
        int r = id >> 3;           // 0..127
        int gr = id & 7;
        CP_ASYNC16(dst + (uint32_t)(r * 128 + ((gr ^ (r & 7)) << 4)),
                   src + (size_t)r * DIMC + gr * 8);
    }
}

__global__ __launch_bounds__(256, 1) void attn_flash_kernel() {
    extern __shared__ char smc[];
    uint32_t sb = smem_u32(smc);

    const int tid = threadIdx.x;
    const int lane = tid & 31;
    const int g = lane >> 2;
    const int tg = lane & 3;
    const int wid = tid >> 5;          // 0..7
    const int wm = wid * 16;
    const int bh = blockIdx.y;
    const int b = bh >> 4;
    const int h = bh & 15;
    const int q0 = blockIdx.x * 128;

    const int a_row = (lane & 7) + ((lane >> 3) & 1) * 8;
    const int a_g   = lane >> 4;
    const int b_row = (lane & 7) + (lane >> 4) * 8;
    const int b_g   = (lane >> 3) & 1;

    const __half* Qg = g_Qh + ((size_t)(b * LC + q0)) * DIMC + h * DHC;
    const __half* Kg = g_Kh + ((size_t)(b * RC)) * DIMC + h * DHC;
    const __half* Vg = g_Vh + ((size_t)(b * RC)) * DIMC + h * DHC;

    // prologue: Q (g0), K0 (g1), V0 (g2)
    attn_load_chunk(sb, Qg, tid);                 CP_COMMIT();
    attn_load_chunk(sb + 16384, Kg, tid);         CP_COMMIT();
    attn_load_chunk(sb + 32768, Vg, tid);         CP_COMMIT();

    CP_WAIT(2);
    __syncthreads();

    // load Q fragments once (16 rows x 64 k = 4 k16-chunks)
    uint32_t qf[4][4];
    {
        int R = wm + a_row;
        uint32_t qbase = sb + (uint32_t)(R * 128);
        int x = R & 7;
#pragma unroll
        for (int k4 = 0; k4 < 4; k4++)
            ldmx4(qf[k4][0], qf[k4][1], qf[k4][2], qf[k4][3],
                  qbase + (uint32_t)(((2 * k4 + a_g) ^ x) << 4));
    }

    float o[8][4];
#pragma unroll
    for (int n = 0; n < 8; n++)
#pragma unroll
        for (int q = 0; q < 4; q++) o[n][q] = 0.f;
    float m0 = -1e30f, m1 = -1e30f, l0 = 0.f, l1 = 0.f;

    for (int c = 0; c < 4; c++) {
        CP_WAIT(1);          // K_c ready (and everything older)
        __syncthreads();     // visibility + all warps past previous PV
        if (c < 3) {         // prefetch next K/V into the other buffers
            attn_load_chunk(sb + 16384 + (uint32_t)(((c + 1) & 1) * 32768),
                            Kg + (size_t)(c + 1) * 128 * DIMC, tid);
            CP_COMMIT();
            attn_load_chunk(sb + 32768 + (uint32_t)(((c + 1) & 1) * 32768),
                            Vg + (size_t)(c + 1) * 128 * DIMC, tid);
            CP_COMMIT();
        }
        uint32_t kbuf = sb + 16384 + (uint32_t)((c & 1) * 32768);

        // ---- S chunk: 16 rows x 128 cols in registers ----
        float e[16][4];
#pragma unroll
        for (int n = 0; n < 16; n++)
#pragma unroll
            for (int q = 0; q < 4; q++) e[n][q] = 0.f;

#pragma unroll
        for (int k4 = 0; k4 < 4; k4++) {
            int Gb = 2 * k4 + b_g;
#pragma unroll
            for (int j = 0; j < 8; j++) {
                int R = 16 * j + b_row;
                uint32_t bb0, bb1, bb2, bb3;
                ldmx4(bb0, bb1, bb2, bb3,
                      kbuf + (uint32_t)(R * 128 + ((Gb ^ (R & 7)) << 4)));
                uint32_t bA[2] = {bb0, bb1}, bB[2] = {bb2, bb3};
                mma_f16(e[2 * j],     qf[k4], bA);
                mma_f16(e[2 * j + 1], qf[k4], bB);
            }
        }

        // ---- online softmax (rows g and g+8; row-mates = quad lanes) ----
        float rm0 = -1e30f, rm1 = -1e30f;
#pragma unroll
        for (int n = 0; n < 16; n++) {
            rm0 = fmaxf(rm0, fmaxf(e[n][0], e[n][1]));
            rm1 = fmaxf(rm1, fmaxf(e[n][2], e[n][3]));
        }
        rm0 = fmaxf(rm0, __shfl_xor_sync(0xffffffffu, rm0, 1));
        rm0 = fmaxf(rm0, __shfl_xor_sync(0xffffffffu, rm0, 2));
        rm1 = fmaxf(rm1, __shfl_xor_sync(0xffffffffu, rm1, 1));
        rm1 = fmaxf(rm1, __shfl_xor_sync(0xffffffffu, rm1, 2));

        float m0n = fmaxf(m0, rm0);
        float m1n = fmaxf(m1, rm1);
        float sc0 = __expf(m0 - m0n);
        float sc1 = __expf(m1 - m1n);
        m0 = m0n; m1 = m1n;

        float s0 = 0.f, s1 = 0.f;
#pragma unroll
        for (int n = 0; n < 16; n++) {
            e[n][0] = __expf(e[n][0] - m0);
            e[n][1] = __expf(e[n][1] - m0);
            e[n][2] = __expf(e[n][2] - m1);
            e[n][3] = __expf(e[n][3] - m1);
            s0 += e[n][0] + e[n][1];
            s1 += e[n][2] + e[n][3];
        }
        l0 = l0 * sc0 + s0;
        l1 = l1 * sc1 + s1;
#pragma unroll
        for (int n = 0; n < 8; n++) {
            o[n][0] *= sc0; o[n][1] *= sc0;
            o[n][2] *= sc1; o[n][3] *= sc1;
        }

        // ---- PV: P (registers, fp16) @ V (ldmatrix.trans) ----
        if (c < 3) { CP_WAIT(2); } else { CP_WAIT(0); }   // V_c ready
        __syncthreads();
        uint32_t vbuf = sb + 32768 + (uint32_t)((c & 1) * 32768);

#pragma unroll
        for (int kk = 0; kk < 128; kk += 16) {
            int n2 = kk >> 3;
            uint32_t pa[4];
            pa[0] = h2u(e[n2][0],     e[n2][1]);
            pa[1] = h2u(e[n2][2],     e[n2][3]);
            pa[2] = h2u(e[n2 + 1][0], e[n2 + 1][1]);
            pa[3] = h2u(e[n2 + 1][2], e[n2 + 1][3]);
            int R = kk + a_row;
            int rx = R & 7;
            uint32_t vrow = vbuf + (uint32_t)(R * 128);
#pragma unroll
            for (int j = 0; j < 4; j++) {
                uint32_t bb0, bb1, bb2, bb3;
                ldmx4t(bb0, bb1, bb2, bb3,
                       vrow + (uint32_t)(((2 * j + a_g) ^ rx) << 4));
                uint32_t bA[2] = {bb0, bb1}, bB[2] = {bb2, bb3};
                mma_f16(o[2 * j],     pa, bA);
                mma_f16(o[2 * j + 1], pa, bB);
            }
        }
    }

    // ---- finalize: reduce l over quad, normalize, store fp16 ----
    l0 += __shfl_xor_sync(0xffffffffu, l0, 1);
    l0 += __shfl_xor_sync(0xffffffffu, l0, 2);
    l1 += __shfl_xor_sync(0xffffffffu, l1, 1);
    l1 += __shfl_xor_sync(0xffffffffu, l1, 2);
    float inv0 = 1.f / l0;
    float inv1 = 1.f / l1;

    __half* Og = g_Oh + ((size_t)(b * LC + q0 + wm + g)) * DIMC + h * DHC;
    __half* Og2 = Og + 8 * DIMC;
#pragma unroll
    for (int n = 0; n < 8; n++) {
        *(__half2*)(Og + n * 8 + tg * 2)  = __floats2half2_rn(o[n][0] * inv0, o[n][1] * inv0);
        *(__half2*)(Og2 + n * 8 + tg * 2) = __floats2half2_rn(o[n][2] * inv1, o[n][3] * inv1);
    }
}

// ---------------------------------------------------------------------------
// Launch
// ---------------------------------------------------------------------------
extern "C" void kernel_launch(void* const* d_in, const int* in_sizes, int n_in,
                              void* d_out, int out_size) {
    const float* x   = (const float*)d_in[0];
    const float* ctx = (const float*)d_in[1];
    const float* Wq  = (const float*)d_in[2];
    const float* Wk  = (const float*)d_in[3];
    const float* Wv  = (const float*)d_in[4];
    const float* Wo  = (const float*)d_in[5];
    float* out = (float*)d_out;

    void *pXr, *pCr, *pWqT, *pWkvT, *pWoT, *pQ, *pK, *pV, *pOh;
    cudaGetSymbolAddress(&pXr, g_Xr);
    cudaGetSymbolAddress(&pCr, g_Cr);
    cudaGetSymbolAddress(&pWqT, g_WqT);
    cudaGetSymbolAddress(&pWkvT, g_WkvT);
    cudaGetSymbolAddress(&pWoT, g_WoT);
    cudaGetSymbolAddress(&pQ, g_Qh);
    cudaGetSymbolAddress(&pK, g_Kh);
    cudaGetSymbolAddress(&pV, g_Vh);
    cudaGetSymbolAddress(&pOh, g_Oh);

    __half* WkvT0 = (__half*)pWkvT;
    __half* WkvT1 = (__half*)pWkvT + (size_t)DIMC * DIMC;

    cudaFuncSetAttribute(mma_gemm_kernel, cudaFuncAttributeMaxDynamicSharedMemorySize, GSM_TOTAL);
    cudaFuncSetAttribute(attn_flash_kernel, cudaFuncAttributeMaxDynamicSharedMemorySize, AFL_SMEM);

    round_copy_h_kernel<<<(BC * LC * DIMC / 4 + 255) / 256, 256>>>(x,   (__half*)pXr, BC * LC * DIMC / 4);  // 0
    round_copy_h_kernel<<<(BC * RC * DIMC / 4 + 255) / 256, 256>>>(ctx, (__half*)pCr, BC * RC * DIMC / 4);  // 1
    dim3 tg3(DIMC / 32, DIMC / 32, 4);
    transpose_all_kernel<<<tg3, 256>>>(Wq, Wk, Wv, Wo,                                                       // 2
                                       (__half*)pWqT, WkvT0, WkvT1, (__half*)pWoT);

    // 3: fused K+V projection (fp16 out)
    mma_gemm_kernel<<<dim3(2 * DIMC / 128, (BC * RC) / 128), 256, GSM_TOTAL>>>(
        (const __half*)pCr, (const __half*)pWkvT, pK, pV, DIMC, 1);
    // 4: Q projection (fp16 out)
    mma_gemm_kernel<<<dim3(DIMC / 128, (BC * LC) / 128), 256, GSM_TOTAL>>>(
        (const __half*)pXr, (const __half*)pWqT, pQ, pQ, 1 << 30, 1);
    // 5: flash attention  <- ncu -s 5 profiles this
    attn_flash_kernel<<<dim3(LC / 128, BC * HC), 256, AFL_SMEM>>>();
    // 6: output projection (fp32 out)
    mma_gemm_kernel<<<dim3(DIMC / 128, (BC * LC) / 128), 256, GSM_TOTAL>>>(
        (const __half*)pOh, (const __half*)pWoT, (void*)out, (void*)out, 1 << 30, 0);
}